// round 1
// baseline (speedup 1.0000x reference)
#include <cuda_runtime.h>
#include <cuda_fp16.h>
#include <mma.h>
#include <math.h>

using namespace nvcuda;

#define BATCH 2
#define SEQ   2048
#define HID   4096
#define NHEAD 32
#define HDIM  128
#define MROWS (BATCH*SEQ)     /* 4096 */
#define QKVN  (3*HID)         /* 12288 */

// ---------------- scratch (static device allocations; no cudaMalloc) ----------------
__device__ __half g_Xhi   [MROWS*HID];
__device__ __half g_Xlo   [MROWS*HID];
__device__ __half g_Wqkvhi[QKVN*HID];
__device__ __half g_Wqkvlo[QKVN*HID];
__device__ __half g_Wohi  [HID*HID];
__device__ __half g_Wolo  [HID*HID];
__device__ float  g_qkv   [MROWS*QKVN];
__device__ __half g_Qhi   [MROWS*HID];
__device__ __half g_Qlo   [MROWS*HID];
__device__ __half g_Khi   [MROWS*HID];
__device__ __half g_Klo   [MROWS*HID];
__device__ __half g_V     [MROWS*HID];
__device__ __half g_AOhi  [MROWS*HID];
__device__ __half g_AOlo  [MROWS*HID];
__device__ float  g_cos   [SEQ*64];
__device__ float  g_sin   [SEQ*64];

__device__ __forceinline__ void splitf(float x, __half &hi, __half &lo) {
    hi = __float2half(x);
    lo = __float2half(x - __half2float(hi));
}

// ---------------- elementwise split kernels ----------------
__device__ __forceinline__ void split_body(const float* __restrict__ src,
                                           __half* __restrict__ hi,
                                           __half* __restrict__ lo, int n) {
    int idx = blockIdx.x * blockDim.x + threadIdx.x;
    if (idx < n) {
        float x = src[idx];
        __half h, l; splitf(x, h, l);
        hi[idx] = h; lo[idx] = l;
    }
}
__global__ void __launch_bounds__(256) split_x_kernel(const float* __restrict__ src) {
    split_body(src, g_Xhi, g_Xlo, MROWS*HID);
}
__global__ void __launch_bounds__(256) split_wqkv_kernel(const float* __restrict__ src) {
    split_body(src, g_Wqkvhi, g_Wqkvlo, QKVN*HID);
}
__global__ void __launch_bounds__(256) split_wo_kernel(const float* __restrict__ src) {
    split_body(src, g_Wohi, g_Wolo, HID*HID);
}

// ---------------- RoPE cos/sin table (match jax fp32 semantics) ----------------
__global__ void __launch_bounds__(256) rope_table_kernel() {
    int idx = blockIdx.x * blockDim.x + threadIdx.x;
    if (idx >= SEQ*64) return;
    int i = idx & 63;
    int s = idx >> 6;
    double inv = pow(10000.0, -((double)(2*i)) / 128.0);
    float invf = (float)inv;
    float ang  = (float)s * invf;         // fp32 rounding like jnp.outer in fp32
    g_cos[idx] = (float)cos((double)ang); // exact cos of that fp32 angle
    g_sin[idx] = (float)sin((double)ang);
}

// ---------------- split fp16 GEMM:  C[M,N] = A[M,K] @ B[N,K]^T  (3-term hi/lo) ----------------
__device__ __forceinline__ void gemm_split_body(
    const __half* __restrict__ Ahi, const __half* __restrict__ Alo,
    const __half* __restrict__ Bhi, const __half* __restrict__ Blo,
    float* __restrict__ C, int M, int N, int K)
{
    __shared__ __half sAh[128][40];
    __shared__ __half sAl[128][40];
    __shared__ __half sBh[128][40];
    __shared__ __half sBl[128][40];

    int tid = threadIdx.x;
    int wid = tid >> 5;
    int bm = blockIdx.y * 128;
    int bn = blockIdx.x * 128;
    int wm = (wid >> 1) * 32;   // 4 warps along M, each 32 rows
    int wn = (wid & 1) * 64;    // 2 warps along N, each 64 cols

    wmma::fragment<wmma::accumulator,16,16,16,float> acc[2][4];
    #pragma unroll
    for (int i = 0; i < 2; i++)
        #pragma unroll
        for (int j = 0; j < 4; j++)
            wmma::fill_fragment(acc[i][j], 0.0f);

    for (int k0 = 0; k0 < K; k0 += 32) {
        #pragma unroll
        for (int v = tid; v < 512; v += 256) {
            int r = v >> 2;
            int c = (v & 3) << 3;
            size_t ga = (size_t)(bm + r) * K + k0 + c;
            size_t gb = (size_t)(bn + r) * K + k0 + c;
            *(int4*)&sAh[r][c] = *(const int4*)&Ahi[ga];
            *(int4*)&sAl[r][c] = *(const int4*)&Alo[ga];
            *(int4*)&sBh[r][c] = *(const int4*)&Bhi[gb];
            *(int4*)&sBl[r][c] = *(const int4*)&Blo[gb];
        }
        __syncthreads();

        #pragma unroll
        for (int kk = 0; kk < 2; kk++) {
            wmma::fragment<wmma::matrix_a,16,16,16,__half,wmma::row_major> ah[2], al[2];
            #pragma unroll
            for (int i = 0; i < 2; i++) {
                wmma::load_matrix_sync(ah[i], &sAh[wm + i*16][kk*16], 40);
                wmma::load_matrix_sync(al[i], &sAl[wm + i*16][kk*16], 40);
            }
            wmma::fragment<wmma::matrix_b,16,16,16,__half,wmma::col_major> bh[4], bl[4];
            #pragma unroll
            for (int j = 0; j < 4; j++) {
                wmma::load_matrix_sync(bh[j], &sBh[wn + j*16][kk*16], 40);
                wmma::load_matrix_sync(bl[j], &sBl[wn + j*16][kk*16], 40);
            }
            #pragma unroll
            for (int i = 0; i < 2; i++)
                #pragma unroll
                for (int j = 0; j < 4; j++) {
                    wmma::mma_sync(acc[i][j], ah[i], bh[j], acc[i][j]);
                    wmma::mma_sync(acc[i][j], ah[i], bl[j], acc[i][j]);
                    wmma::mma_sync(acc[i][j], al[i], bh[j], acc[i][j]);
                }
        }
        __syncthreads();
    }

    #pragma unroll
    for (int i = 0; i < 2; i++)
        #pragma unroll
        for (int j = 0; j < 4; j++) {
            size_t off = (size_t)(bm + wm + i*16) * N + bn + wn + j*16;
            wmma::store_matrix_sync(&C[off], acc[i][j], N, wmma::mem_row_major);
        }
}

__global__ void __launch_bounds__(256) gemm_qkv_kernel() {
    gemm_split_body(g_Xhi, g_Xlo, g_Wqkvhi, g_Wqkvlo, g_qkv, MROWS, QKVN, HID);
}
__global__ void __launch_bounds__(256) gemm_out_kernel(float* __restrict__ out) {
    gemm_split_body(g_AOhi, g_AOlo, g_Wohi, g_Wolo, out, MROWS, HID, HID);
}

// ---------------- RoPE + transpose to [B,NH,S,D], split to hi/lo ----------------
__global__ void __launch_bounds__(256) rope_transpose_kernel() {
    int idx = blockIdx.x * blockDim.x + threadIdx.x;
    if (idx >= BATCH*SEQ*NHEAD*64) return;
    int i = idx & 63;
    int h = (idx >> 6) & 31;
    int s = (idx >> 11) & 2047;
    int b = idx >> 22;

    size_t row  = (size_t)b * SEQ + s;
    size_t base = row * QKVN + (size_t)h * HDIM;

    float q1 = g_qkv[base + i],         q2 = g_qkv[base + i + 64];
    float k1 = g_qkv[base + HID + i],   k2 = g_qkv[base + HID + i + 64];
    float v1 = g_qkv[base + 2*HID + i], v2 = g_qkv[base + 2*HID + i + 64];

    float c  = g_cos[s*64 + i];
    float sn = g_sin[s*64 + i];

    size_t dst = (((size_t)b * NHEAD + h) * SEQ + s) * HDIM + i;

    __half hi, lo;
    splitf(q1*c - q2*sn, hi, lo); g_Qhi[dst]     = hi; g_Qlo[dst]     = lo;
    splitf(q1*sn + q2*c, hi, lo); g_Qhi[dst+64]  = hi; g_Qlo[dst+64]  = lo;
    splitf(k1*c - k2*sn, hi, lo); g_Khi[dst]     = hi; g_Klo[dst]     = lo;
    splitf(k1*sn + k2*c, hi, lo); g_Khi[dst+64]  = hi; g_Klo[dst+64]  = lo;
    g_V[dst]    = __float2half(v1);
    g_V[dst+64] = __float2half(v2);
}

// ---------------- flash attention, 64-row q tiles, causal ----------------
// smem layout (bytes): Qh/Ql/Kh/Kl/V: 5 * 64*136*2 ; S: 64*68*4 ; P: 64*72*2 ; O: 64*132*4 ; m/l/alpha: 3*64*4
#define FL_SMEM (5*64*136*2 + 64*68*4 + 64*72*2 + 64*132*4 + 3*64*4)

__global__ void __launch_bounds__(256) flash_kernel() {
    extern __shared__ unsigned char smraw[];
    __half* sQh = (__half*)smraw;
    __half* sQl = sQh + 64*136;
    __half* sKh = sQl + 64*136;
    __half* sKl = sKh + 64*136;
    __half* sV  = sKl + 64*136;
    float*  sS  = (float*)(sV + 64*136);
    __half* sP  = (__half*)(sS + 64*68);
    float*  sO  = (float*)(sP + 64*72);
    float*  smx = sO + 64*132;
    float*  sl  = smx + 64;
    float*  sal = sl + 64;

    int tid = threadIdx.x;
    int wid = tid >> 5;
    int qt  = blockIdx.x;
    int h   = blockIdx.y;
    int b   = blockIdx.z;
    int bh  = b * NHEAD + h;
    int q0  = qt * 64;

    const float scale = 0.08838834764831845f; // 1/sqrt(128)

    // load Q tile
    {
        const __half* Qh = g_Qhi + ((size_t)bh * SEQ + q0) * HDIM;
        const __half* Ql = g_Qlo + ((size_t)bh * SEQ + q0) * HDIM;
        for (int v = tid; v < 1024; v += 256) {
            int r = v >> 4, c = (v & 15) << 3;
            *(int4*)(sQh + r*136 + c) = *(const int4*)(Qh + r*HDIM + c);
            *(int4*)(sQl + r*136 + c) = *(const int4*)(Ql + r*HDIM + c);
        }
    }
    for (int v = tid; v < 64*132; v += 256) sO[v] = 0.0f;
    if (tid < 64) { smx[tid] = -INFINITY; sl[tid] = 0.0f; }
    __syncthreads();

    int wm = (wid >> 1) * 16;   // warp row block (4 warps over 64 rows)

    for (int kt = 0; kt <= qt; kt++) {
        int k0 = kt * 64;
        // load K hi/lo + V tiles
        {
            const __half* Kh = g_Khi + ((size_t)bh * SEQ + k0) * HDIM;
            const __half* Kl = g_Klo + ((size_t)bh * SEQ + k0) * HDIM;
            const __half* Vp = g_V   + ((size_t)bh * SEQ + k0) * HDIM;
            for (int v = tid; v < 1024; v += 256) {
                int r = v >> 4, c = (v & 15) << 3;
                *(int4*)(sKh + r*136 + c) = *(const int4*)(Kh + r*HDIM + c);
                *(int4*)(sKl + r*136 + c) = *(const int4*)(Kl + r*HDIM + c);
                *(int4*)(sV  + r*136 + c) = *(const int4*)(Vp + r*HDIM + c);
            }
        }
        __syncthreads();

        // S = Q K^T (3-term split), 64x64 fp32
        {
            int wn = (wid & 1) * 32;
            wmma::fragment<wmma::accumulator,16,16,16,float> sacc[2];
            wmma::fill_fragment(sacc[0], 0.0f);
            wmma::fill_fragment(sacc[1], 0.0f);
            #pragma unroll
            for (int d8 = 0; d8 < 8; d8++) {
                wmma::fragment<wmma::matrix_a,16,16,16,__half,wmma::row_major> ah, al;
                wmma::load_matrix_sync(ah, sQh + wm*136 + d8*16, 136);
                wmma::load_matrix_sync(al, sQl + wm*136 + d8*16, 136);
                #pragma unroll
                for (int j = 0; j < 2; j++) {
                    wmma::fragment<wmma::matrix_b,16,16,16,__half,wmma::col_major> kh, kl;
                    wmma::load_matrix_sync(kh, sKh + (wn + j*16)*136 + d8*16, 136);
                    wmma::load_matrix_sync(kl, sKl + (wn + j*16)*136 + d8*16, 136);
                    wmma::mma_sync(sacc[j], ah, kh, sacc[j]);
                    wmma::mma_sync(sacc[j], ah, kl, sacc[j]);
                    wmma::mma_sync(sacc[j], al, kh, sacc[j]);
                }
            }
            wmma::store_matrix_sync(sS + wm*68 + wn,      sacc[0], 68, wmma::mem_row_major);
            wmma::store_matrix_sync(sS + wm*68 + wn + 16, sacc[1], 68, wmma::mem_row_major);
        }
        __syncthreads();

        // online softmax: 4 threads per row
        {
            int r    = tid >> 2;
            int lane = tid & 3;
            bool diag = (kt == qt);
            int jmax = diag ? (r + 1) : 64;   // valid j: k0+j <= q0+r  <=>  j <= r on diagonal

            float lm = -INFINITY;
            #pragma unroll
            for (int jj = 0; jj < 16; jj++) {
                int j = lane*16 + jj;
                if (j < jmax) lm = fmaxf(lm, sS[r*68 + j] * scale);
            }
            lm = fmaxf(lm, __shfl_xor_sync(0xffffffffu, lm, 1));
            lm = fmaxf(lm, __shfl_xor_sync(0xffffffffu, lm, 2));
            float mo = smx[r];
            float mn = fmaxf(mo, lm);

            float rl = 0.0f;
            #pragma unroll
            for (int jj = 0; jj < 16; jj++) {
                int j = lane*16 + jj;
                float p = 0.0f;
                if (j < jmax) { p = expf(sS[r*68 + j] * scale - mn); rl += p; }
                sP[r*72 + j] = __float2half(p);
            }
            rl += __shfl_xor_sync(0xffffffffu, rl, 1);
            rl += __shfl_xor_sync(0xffffffffu, rl, 2);

            if (lane == 0) {
                float a = expf(mo - mn);
                sal[r] = a;
                smx[r] = mn;
                sl[r]  = sl[r] * a + rl;
            }
        }
        __syncthreads();

        // rescale O accumulator
        for (int v = tid; v < 64*128; v += 256) {
            int r = v >> 7, d = v & 127;
            sO[r*132 + d] *= sal[r];
        }
        __syncthreads();

        // O += P @ V
        {
            int wn2 = (wid & 1) * 64;
            wmma::fragment<wmma::accumulator,16,16,16,float> oc[4];
            #pragma unroll
            for (int j = 0; j < 4; j++)
                wmma::load_matrix_sync(oc[j], sO + wm*132 + wn2 + j*16, 132, wmma::mem_row_major);
            #pragma unroll
            for (int kk = 0; kk < 4; kk++) {
                wmma::fragment<wmma::matrix_a,16,16,16,__half,wmma::row_major> pf;
                wmma::load_matrix_sync(pf, sP + wm*72 + kk*16, 72);
                #pragma unroll
                for (int j = 0; j < 4; j++) {
                    wmma::fragment<wmma::matrix_b,16,16,16,__half,wmma::row_major> vf;
                    wmma::load_matrix_sync(vf, sV + (kk*16)*136 + wn2 + j*16, 136);
                    wmma::mma_sync(oc[j], pf, vf, oc[j]);
                }
            }
            #pragma unroll
            for (int j = 0; j < 4; j++)
                wmma::store_matrix_sync(sO + wm*132 + wn2 + j*16, oc[j], 132, wmma::mem_row_major);
        }
        __syncthreads();
    }

    // epilogue: normalize, merge heads to [B,S,H], split to hi/lo
    for (int v = tid; v < 64*128; v += 256) {
        int r = v >> 7, d = v & 127;
        float o = sO[r*132 + d] / sl[r];
        size_t dst = ((size_t)b * SEQ + q0 + r) * HID + (size_t)h * HDIM + d;
        __half hi, lo; splitf(o, hi, lo);
        g_AOhi[dst] = hi; g_AOlo[dst] = lo;
    }
}

// ---------------- launch ----------------
extern "C" void kernel_launch(void* const* d_in, const int* in_sizes, int n_in,
                              void* d_out, int out_size) {
    const float* X    = (const float*)d_in[0];
    const float* Wqkv = (const float*)d_in[1];
    const float* Wo   = (const float*)d_in[2];
    // d_in[3] = attention_mask: exactly causal with -1e9; handled analytically.

    cudaFuncSetAttribute(flash_kernel, cudaFuncAttributeMaxDynamicSharedMemorySize, FL_SMEM);

    split_x_kernel   <<<(MROWS*HID + 255)/256, 256>>>(X);
    split_wqkv_kernel<<<(QKVN*HID  + 255)/256, 256>>>(Wqkv);
    split_wo_kernel  <<<(HID*HID   + 255)/256, 256>>>(Wo);
    rope_table_kernel<<<(SEQ*64    + 255)/256, 256>>>();

    gemm_qkv_kernel<<<dim3(QKVN/128, MROWS/128), 256>>>();

    rope_transpose_kernel<<<(BATCH*SEQ*NHEAD*64 + 255)/256, 256>>>();

    flash_kernel<<<dim3(SEQ/64, NHEAD, BATCH), 256, FL_SMEM>>>();

    gemm_out_kernel<<<dim3(HID/128, MROWS/128), 256>>>((float*)d_out);
}

// round 3
// speedup vs baseline: 1.4225x; 1.4225x over previous
#include <cuda_runtime.h>
#include <cuda_fp16.h>
#include <mma.h>
#include <math.h>
#include <stdint.h>

using namespace nvcuda;

#define BATCH 2
#define SEQ   2048
#define HID   4096
#define NHEAD 32
#define HDIM  128
#define MROWS (BATCH*SEQ)     /* 4096 */
#define QKVN  (3*HID)         /* 12288 */

// ---------------- scratch (static device allocations; no cudaMalloc) ----------------
__device__ __half g_Xhi   [MROWS*HID];
__device__ __half g_Xlo   [MROWS*HID];
__device__ __half g_Wqkvhi[QKVN*HID];
__device__ __half g_Wqkvlo[QKVN*HID];
__device__ __half g_Wohi  [HID*HID];
__device__ __half g_Wolo  [HID*HID];
__device__ float  g_qkv   [MROWS*QKVN];
__device__ __half g_Qhi   [MROWS*HID];
__device__ __half g_Qlo   [MROWS*HID];
__device__ __half g_Khi   [MROWS*HID];
__device__ __half g_Klo   [MROWS*HID];
__device__ __half g_V     [MROWS*HID];
__device__ __half g_AOhi  [MROWS*HID];
__device__ __half g_AOlo  [MROWS*HID];
__device__ float  g_cos   [SEQ*64];
__device__ float  g_sin   [SEQ*64];

__device__ __forceinline__ void splitf(float x, __half &hi, __half &lo) {
    hi = __float2half(x);
    lo = __float2half(x - __half2float(hi));
}

// ---------------- cp.async helpers (sm_80 baseline — safe on this toolchain) ----------------
static __device__ __forceinline__ uint32_t smem_u32(const void* p) {
    uint32_t a;
    asm("{ .reg .u64 t; cvta.to.shared.u64 t, %1; cvt.u32.u64 %0, t; }" : "=r"(a) : "l"(p));
    return a;
}
static __device__ __forceinline__ void cp_async16(uint32_t dst, const void* src) {
    asm volatile("cp.async.cg.shared.global [%0], [%1], 16;\n" :: "r"(dst), "l"(src));
}
#define CP_COMMIT() asm volatile("cp.async.commit_group;\n" ::: "memory")
#define CP_WAIT1()  asm volatile("cp.async.wait_group 1;\n" ::: "memory")

// ---------------- elementwise split kernels ----------------
__device__ __forceinline__ void split_body(const float* __restrict__ src,
                                           __half* __restrict__ hi,
                                           __half* __restrict__ lo, int n) {
    int idx = blockIdx.x * blockDim.x + threadIdx.x;
    if (idx < n) {
        float x = src[idx];
        __half h, l; splitf(x, h, l);
        hi[idx] = h; lo[idx] = l;
    }
}
__global__ void __launch_bounds__(256) split_x_kernel(const float* __restrict__ src) {
    split_body(src, g_Xhi, g_Xlo, MROWS*HID);
}
__global__ void __launch_bounds__(256) split_wqkv_kernel(const float* __restrict__ src) {
    split_body(src, g_Wqkvhi, g_Wqkvlo, QKVN*HID);
}
__global__ void __launch_bounds__(256) split_wo_kernel(const float* __restrict__ src) {
    split_body(src, g_Wohi, g_Wolo, HID*HID);
}

// ---------------- RoPE cos/sin table (match jax fp32 semantics) ----------------
__global__ void __launch_bounds__(256) rope_table_kernel() {
    int idx = blockIdx.x * blockDim.x + threadIdx.x;
    if (idx >= SEQ*64) return;
    int i = idx & 63;
    int s = idx >> 6;
    double inv = pow(10000.0, -((double)(2*i)) / 128.0);
    float invf = (float)inv;
    float ang  = (float)s * invf;
    g_cos[idx] = (float)cos((double)ang);
    g_sin[idx] = (float)sin((double)ang);
}

// =====================================================================
//  Pipelined split-fp16 GEMM:  C[M,N](fp32) = Ahi/lo[M,K] @ (Bhi/lo[N,K])^T
//  3-term: AhiBhi + AhiBlo + AloBhi. wmma (HMMA) + 3-stage cp.async.
//  CTA tile 128x128, K-chunk 32.
// =====================================================================

#define KC        32
#define GSTAGES   3
#define ARR_HALF  (128*40)               /* padded: 32 halves data + 8 pad */
#define ARR_BYTES (ARR_HALF*2)           /* 10240 */
#define STAGE_BYTES (4*ARR_BYTES)        /* 40960 */
#define GEMM_SMEM (GSTAGES*STAGE_BYTES)  /* 122880 */

static __device__ __forceinline__ void gemm_load_stage(
    uint32_t stage_base, int tid,
    const __half* __restrict__ Ahi, const __half* __restrict__ Alo,
    const __half* __restrict__ Bhi, const __half* __restrict__ Blo,
    int bm, int bn, int K, int k0)
{
    const __half* srcs[4];
    srcs[0] = Ahi + (size_t)bm * K + k0;
    srcs[1] = Alo + (size_t)bm * K + k0;
    srcs[2] = Bhi + (size_t)bn * K + k0;
    srcs[3] = Blo + (size_t)bn * K + k0;
    int chunk = tid & 3;          // 16B chunk within 64B row of data
    int r0    = tid >> 2;         // rows 0..63, second pass +64
    #pragma unroll
    for (int rg = 0; rg < 4; rg++) {
        uint32_t dstb = stage_base + rg * ARR_BYTES;
        const char* gb = (const char*)srcs[rg] + chunk * 16;
        #pragma unroll
        for (int u = 0; u < 2; u++) {
            int row = r0 + u * 64;
            cp_async16(dstb + row * 80 + chunk * 16, gb + (size_t)row * K * 2);
        }
    }
}

__global__ void __launch_bounds__(256, 1) gemm_pipe_kernel(
    const __half* __restrict__ Ahi, const __half* __restrict__ Alo,
    const __half* __restrict__ Bhi, const __half* __restrict__ Blo,
    float* __restrict__ C, int M, int N, int K, int grid_m, int grid_n)
{
    extern __shared__ __half smh[];
    uint32_t smem_base = smem_u32(smh);
    int tid = threadIdx.x;
    int wid = tid >> 5;

    // grouped rasterization for L2 reuse
    int pid = blockIdx.x;
    const int GRPW = 8;
    int width = GRPW * grid_n;
    int g   = pid / width;
    int rem = pid - g * width;
    int gm  = grid_m - g * GRPW; if (gm > GRPW) gm = GRPW;
    int bm  = (g * GRPW + (rem % gm)) * 128;
    int bn  = (rem / gm) * 128;

    int wm = (wid >> 1) * 32;   // 4 warps along M
    int wn = (wid & 1) * 64;    // 2 warps along N

    wmma::fragment<wmma::accumulator,16,16,16,float> acc[2][4];
    #pragma unroll
    for (int i = 0; i < 2; i++)
        #pragma unroll
        for (int j = 0; j < 4; j++)
            wmma::fill_fragment(acc[i][j], 0.0f);

    const int NIT = K / KC;

    gemm_load_stage(smem_base,               tid, Ahi, Alo, Bhi, Blo, bm, bn, K, 0);
    CP_COMMIT();
    gemm_load_stage(smem_base + STAGE_BYTES, tid, Ahi, Alo, Bhi, Blo, bm, bn, K, KC);
    CP_COMMIT();

    for (int it = 0; it < NIT; it++) {
        CP_WAIT1();
        __syncthreads();

        int nxt = it + 2;
        if (nxt < NIT)
            gemm_load_stage(smem_base + (uint32_t)(nxt % GSTAGES) * STAGE_BYTES, tid,
                            Ahi, Alo, Bhi, Blo, bm, bn, K, nxt * KC);
        CP_COMMIT();

        const __half* st  = smh + (size_t)(it % GSTAGES) * (STAGE_BYTES / 2);
        const __half* sAh = st;
        const __half* sAl = st + ARR_HALF;
        const __half* sBh = st + 2*ARR_HALF;
        const __half* sBl = st + 3*ARR_HALF;

        #pragma unroll
        for (int kk = 0; kk < 2; kk++) {
            wmma::fragment<wmma::matrix_a,16,16,16,__half,wmma::row_major> ah[2], al[2];
            #pragma unroll
            for (int i = 0; i < 2; i++) {
                wmma::load_matrix_sync(ah[i], sAh + (wm + i*16)*40 + kk*16, 40);
                wmma::load_matrix_sync(al[i], sAl + (wm + i*16)*40 + kk*16, 40);
            }
            wmma::fragment<wmma::matrix_b,16,16,16,__half,wmma::col_major> bh[4], bl[4];
            #pragma unroll
            for (int j = 0; j < 4; j++) {
                wmma::load_matrix_sync(bh[j], sBh + (wn + j*16)*40 + kk*16, 40);
                wmma::load_matrix_sync(bl[j], sBl + (wn + j*16)*40 + kk*16, 40);
            }
            #pragma unroll
            for (int i = 0; i < 2; i++)
                #pragma unroll
                for (int j = 0; j < 4; j++) {
                    wmma::mma_sync(acc[i][j], ah[i], bh[j], acc[i][j]);
                    wmma::mma_sync(acc[i][j], ah[i], bl[j], acc[i][j]);
                    wmma::mma_sync(acc[i][j], al[i], bh[j], acc[i][j]);
                }
        }
        __syncthreads();
    }

    #pragma unroll
    for (int i = 0; i < 2; i++)
        #pragma unroll
        for (int j = 0; j < 4; j++) {
            size_t off = (size_t)(bm + wm + i*16) * N + bn + wn + j*16;
            wmma::store_matrix_sync(&C[off], acc[i][j], N, wmma::mem_row_major);
        }
}

// ---------------- RoPE + transpose to [B,NH,S,D], split to hi/lo ----------------
__global__ void __launch_bounds__(256) rope_transpose_kernel() {
    int idx = blockIdx.x * blockDim.x + threadIdx.x;
    if (idx >= BATCH*SEQ*NHEAD*64) return;
    int i = idx & 63;
    int h = (idx >> 6) & 31;
    int s = (idx >> 11) & 2047;
    int b = idx >> 22;

    size_t row  = (size_t)b * SEQ + s;
    size_t base = row * QKVN + (size_t)h * HDIM;

    float q1 = g_qkv[base + i],         q2 = g_qkv[base + i + 64];
    float k1 = g_qkv[base + HID + i],   k2 = g_qkv[base + HID + i + 64];
    float v1 = g_qkv[base + 2*HID + i], v2 = g_qkv[base + 2*HID + i + 64];

    float c  = g_cos[s*64 + i];
    float sn = g_sin[s*64 + i];

    size_t dst = (((size_t)b * NHEAD + h) * SEQ + s) * HDIM + i;

    __half hi, lo;
    splitf(q1*c - q2*sn, hi, lo); g_Qhi[dst]     = hi; g_Qlo[dst]     = lo;
    splitf(q1*sn + q2*c, hi, lo); g_Qhi[dst+64]  = hi; g_Qlo[dst+64]  = lo;
    splitf(k1*c - k2*sn, hi, lo); g_Khi[dst]     = hi; g_Klo[dst]     = lo;
    splitf(k1*sn + k2*c, hi, lo); g_Khi[dst+64]  = hi; g_Klo[dst+64]  = lo;
    g_V[dst]    = __float2half(v1);
    g_V[dst+64] = __float2half(v2);
}

// ---------------- flash attention, 64-row q tiles, causal, cp.async double buffer ----------------
// smem halves: Qh,Ql + 2x(Kh,Kl,V) = 8 * 64*136 ; floats: S 64*68, O 64*132, m/l/a 3*64 ; halves P 64*72
#define TILE_H   (64*136)                 /* halves per tile array */
#define TILE_B   (TILE_H*2)               /* 17408 bytes */
#define FL_SMEM  (8*TILE_B + 64*68*4 + 64*72*2 + 64*132*4 + 3*64*4)

static __device__ __forceinline__ void flash_issue_tile(
    uint32_t dKh, uint32_t dKl, uint32_t dV,
    const __half* __restrict__ Kh, const __half* __restrict__ Kl,
    const __half* __restrict__ V, int tid)
{
    int chunk = tid & 15;    // 16 chunks of 16B per 256B row
    int r0    = tid >> 4;    // 16 rows per pass, 4 passes
    #pragma unroll
    for (int u = 0; u < 4; u++) {
        int r = r0 + u * 16;
        uint32_t so = (uint32_t)(r * 272 + chunk * 16);
        size_t   go = (size_t)r * HDIM * 2 + chunk * 16;
        cp_async16(dKh + so, (const char*)Kh + go);
        cp_async16(dKl + so, (const char*)Kl + go);
        cp_async16(dV  + so, (const char*)V  + go);
    }
}

__global__ void __launch_bounds__(256) flash_kernel() {
    extern __shared__ unsigned char smraw[];
    __half* sQh = (__half*)smraw;
    __half* sQl = sQh + TILE_H;
    __half* sKB = sQl + TILE_H;              // 2 buffers x (Kh,Kl,V)
    float*  sS  = (float*)(sKB + 6*TILE_H);
    __half* sP  = (__half*)(sS + 64*68);
    float*  sO  = (float*)(sP + 64*72);
    float*  smx = sO + 64*132;
    float*  sl  = smx + 64;
    float*  sal = sl + 64;

    int tid = threadIdx.x;
    int wid = tid >> 5;
    int qt  = blockIdx.x;
    int h   = blockIdx.y;
    int b   = blockIdx.z;
    int bh  = b * NHEAD + h;
    int q0  = qt * 64;

    const float scale = 0.08838834764831845f;

    const __half* Khg = g_Khi + (size_t)bh * SEQ * HDIM;
    const __half* Klg = g_Klo + (size_t)bh * SEQ * HDIM;
    const __half* Vg  = g_V   + (size_t)bh * SEQ * HDIM;

    uint32_t sKB_u = smem_u32(sKB);

    // prefetch tile 0
    flash_issue_tile(sKB_u, sKB_u + TILE_B, sKB_u + 2*TILE_B,
                     Khg, Klg, Vg, tid);
    CP_COMMIT();

    // load Q tile + init
    {
        const __half* Qh = g_Qhi + ((size_t)bh * SEQ + q0) * HDIM;
        const __half* Ql = g_Qlo + ((size_t)bh * SEQ + q0) * HDIM;
        for (int v = tid; v < 1024; v += 256) {
            int r = v >> 4, c = (v & 15) << 3;
            *(int4*)(sQh + r*136 + c) = *(const int4*)(Qh + r*HDIM + c);
            *(int4*)(sQl + r*136 + c) = *(const int4*)(Ql + r*HDIM + c);
        }
    }
    for (int v = tid; v < 64*132; v += 256) sO[v] = 0.0f;
    if (tid < 64) { smx[tid] = -INFINITY; sl[tid] = 0.0f; }

    int wm = (wid >> 1) * 16;

    for (int kt = 0; kt <= qt; kt++) {
        // prefetch next tile into alternate buffer
        if (kt + 1 <= qt) {
            uint32_t nb = sKB_u + (uint32_t)((kt + 1) & 1) * 3 * TILE_B;
            flash_issue_tile(nb, nb + TILE_B, nb + 2*TILE_B,
                             Khg + (size_t)(kt+1)*64*HDIM,
                             Klg + (size_t)(kt+1)*64*HDIM,
                             Vg  + (size_t)(kt+1)*64*HDIM, tid);
        }
        CP_COMMIT();
        CP_WAIT1();
        __syncthreads();

        __half* sKh = sKB + (size_t)(kt & 1) * 3 * TILE_H;
        __half* sKl = sKh + TILE_H;
        __half* sV  = sKh + 2*TILE_H;

        // S = Q K^T (3-term split)
        {
            int wn = (wid & 1) * 32;
            wmma::fragment<wmma::accumulator,16,16,16,float> sacc[2];
            wmma::fill_fragment(sacc[0], 0.0f);
            wmma::fill_fragment(sacc[1], 0.0f);
            #pragma unroll
            for (int d8 = 0; d8 < 8; d8++) {
                wmma::fragment<wmma::matrix_a,16,16,16,__half,wmma::row_major> ah, al;
                wmma::load_matrix_sync(ah, sQh + wm*136 + d8*16, 136);
                wmma::load_matrix_sync(al, sQl + wm*136 + d8*16, 136);
                #pragma unroll
                for (int j = 0; j < 2; j++) {
                    wmma::fragment<wmma::matrix_b,16,16,16,__half,wmma::col_major> kh, kl;
                    wmma::load_matrix_sync(kh, sKh + (wn + j*16)*136 + d8*16, 136);
                    wmma::load_matrix_sync(kl, sKl + (wn + j*16)*136 + d8*16, 136);
                    wmma::mma_sync(sacc[j], ah, kh, sacc[j]);
                    wmma::mma_sync(sacc[j], ah, kl, sacc[j]);
                    wmma::mma_sync(sacc[j], al, kh, sacc[j]);
                }
            }
            wmma::store_matrix_sync(sS + wm*68 + wn,      sacc[0], 68, wmma::mem_row_major);
            wmma::store_matrix_sync(sS + wm*68 + wn + 16, sacc[1], 68, wmma::mem_row_major);
        }
        __syncthreads();

        // online softmax: 4 threads per row
        {
            int r    = tid >> 2;
            int lane = tid & 3;
            bool diag = (kt == qt);
            int jmax = diag ? (r + 1) : 64;

            float lm = -INFINITY;
            #pragma unroll
            for (int jj = 0; jj < 16; jj++) {
                int j = lane*16 + jj;
                if (j < jmax) lm = fmaxf(lm, sS[r*68 + j] * scale);
            }
            lm = fmaxf(lm, __shfl_xor_sync(0xffffffffu, lm, 1));
            lm = fmaxf(lm, __shfl_xor_sync(0xffffffffu, lm, 2));
            float mo = smx[r];
            float mn = fmaxf(mo, lm);

            float rl = 0.0f;
            #pragma unroll
            for (int jj = 0; jj < 16; jj++) {
                int j = lane*16 + jj;
                float p = 0.0f;
                if (j < jmax) { p = expf(sS[r*68 + j] * scale - mn); rl += p; }
                sP[r*72 + j] = __float2half(p);
            }
            rl += __shfl_xor_sync(0xffffffffu, rl, 1);
            rl += __shfl_xor_sync(0xffffffffu, rl, 2);

            if (lane == 0) {
                float a = expf(mo - mn);
                sal[r] = a;
                smx[r] = mn;
                sl[r]  = sl[r] * a + rl;
            }
        }
        __syncthreads();

        // rescale O accumulator
        for (int v = tid; v < 64*128; v += 256) {
            int r = v >> 7, d = v & 127;
            sO[r*132 + d] *= sal[r];
        }
        __syncthreads();

        // O += P @ V
        {
            int wn2 = (wid & 1) * 64;
            wmma::fragment<wmma::accumulator,16,16,16,float> oc[4];
            #pragma unroll
            for (int j = 0; j < 4; j++)
                wmma::load_matrix_sync(oc[j], sO + wm*132 + wn2 + j*16, 132, wmma::mem_row_major);
            #pragma unroll
            for (int kk = 0; kk < 4; kk++) {
                wmma::fragment<wmma::matrix_a,16,16,16,__half,wmma::row_major> pf;
                wmma::load_matrix_sync(pf, sP + wm*72 + kk*16, 72);
                #pragma unroll
                for (int j = 0; j < 4; j++) {
                    wmma::fragment<wmma::matrix_b,16,16,16,__half,wmma::row_major> vf;
                    wmma::load_matrix_sync(vf, sV + (kk*16)*136 + wn2 + j*16, 136);
                    wmma::mma_sync(oc[j], pf, vf, oc[j]);
                }
            }
            #pragma unroll
            for (int j = 0; j < 4; j++)
                wmma::store_matrix_sync(sO + wm*132 + wn2 + j*16, oc[j], 132, wmma::mem_row_major);
        }
        __syncthreads();
    }

    // epilogue: normalize, merge heads to [B,S,H], split to hi/lo
    for (int v = tid; v < 64*128; v += 256) {
        int r = v >> 7, d = v & 127;
        float o = sO[r*132 + d] / sl[r];
        size_t dst = ((size_t)b * SEQ + q0 + r) * HID + (size_t)h * HDIM + d;
        __half hi, lo; splitf(o, hi, lo);
        g_AOhi[dst] = hi; g_AOlo[dst] = lo;
    }
}

// ---------------- launch ----------------
extern "C" void kernel_launch(void* const* d_in, const int* in_sizes, int n_in,
                              void* d_out, int out_size) {
    const float* X    = (const float*)d_in[0];
    const float* Wqkv = (const float*)d_in[1];
    const float* Wo   = (const float*)d_in[2];

    cudaFuncSetAttribute(flash_kernel, cudaFuncAttributeMaxDynamicSharedMemorySize, FL_SMEM);
    cudaFuncSetAttribute(gemm_pipe_kernel, cudaFuncAttributeMaxDynamicSharedMemorySize, GEMM_SMEM);

    __half *Xhi, *Xlo, *Wqh, *Wql, *Woh, *Wol, *AOh, *AOl;
    float  *qkv;
    cudaGetSymbolAddress((void**)&Xhi, g_Xhi);
    cudaGetSymbolAddress((void**)&Xlo, g_Xlo);
    cudaGetSymbolAddress((void**)&Wqh, g_Wqkvhi);
    cudaGetSymbolAddress((void**)&Wql, g_Wqkvlo);
    cudaGetSymbolAddress((void**)&Woh, g_Wohi);
    cudaGetSymbolAddress((void**)&Wol, g_Wolo);
    cudaGetSymbolAddress((void**)&AOh, g_AOhi);
    cudaGetSymbolAddress((void**)&AOl, g_AOlo);
    cudaGetSymbolAddress((void**)&qkv, g_qkv);

    split_x_kernel   <<<(MROWS*HID + 255)/256, 256>>>(X);
    split_wqkv_kernel<<<(QKVN*HID  + 255)/256, 256>>>(Wqkv);
    split_wo_kernel  <<<(HID*HID   + 255)/256, 256>>>(Wo);
    rope_table_kernel<<<(SEQ*64    + 255)/256, 256>>>();

    // QKV projection: M=4096, N=12288, K=4096
    gemm_pipe_kernel<<<(MROWS/128)*(QKVN/128), 256, GEMM_SMEM>>>(
        Xhi, Xlo, Wqh, Wql, qkv, MROWS, QKVN, HID, MROWS/128, QKVN/128);

    rope_transpose_kernel<<<(BATCH*SEQ*NHEAD*64 + 255)/256, 256>>>();

    flash_kernel<<<dim3(SEQ/64, NHEAD, BATCH), 256, FL_SMEM>>>();

    // Output projection: M=4096, N=4096, K=4096
    gemm_pipe_kernel<<<(MROWS/128)*(HID/128), 256, GEMM_SMEM>>>(
        AOh, AOl, Woh, Wol, (float*)d_out, MROWS, HID, HID, MROWS/128, HID/128);
}

// round 4
// speedup vs baseline: 1.6048x; 1.1282x over previous
#include <cuda_runtime.h>
#include <cuda_fp16.h>
#include <mma.h>
#include <math.h>
#include <stdint.h>

using namespace nvcuda;

#define BATCH 2
#define SEQ   2048
#define HID   4096
#define NHEAD 32
#define HDIM  128
#define MROWS (BATCH*SEQ)     /* 4096 */
#define QKVN  (3*HID)         /* 12288 */

// ---------------- scratch ----------------
__device__ __half g_Xhi   [MROWS*HID];
__device__ __half g_Xlo   [MROWS*HID];
__device__ __half g_Wqkvhi[QKVN*HID];
__device__ __half g_Wqkvlo[QKVN*HID];
__device__ __half g_Wohi  [HID*HID];
__device__ __half g_Wolo  [HID*HID];
__device__ float  g_qkv   [MROWS*QKVN];
__device__ __half g_Qhi   [MROWS*HID];
__device__ __half g_Qlo   [MROWS*HID];
__device__ __half g_Khi   [MROWS*HID];
__device__ __half g_Klo   [MROWS*HID];
__device__ __half g_V     [MROWS*HID];
__device__ __half g_AOhi  [MROWS*HID];
__device__ __half g_AOlo  [MROWS*HID];
__device__ float  g_cos   [SEQ*64];
__device__ float  g_sin   [SEQ*64];

__device__ __forceinline__ void splitf(float x, __half &hi, __half &lo) {
    hi = __float2half(x);
    lo = __float2half(x - __half2float(hi));
}

// ---------------- cp.async helpers ----------------
static __device__ __forceinline__ uint32_t smem_u32(const void* p) {
    uint32_t a;
    asm("{ .reg .u64 t; cvta.to.shared.u64 t, %1; cvt.u32.u64 %0, t; }" : "=r"(a) : "l"(p));
    return a;
}
static __device__ __forceinline__ void cp_async16(uint32_t dst, const void* src) {
    asm volatile("cp.async.cg.shared.global [%0], [%1], 16;\n" :: "r"(dst), "l"(src));
}
#define CP_COMMIT() asm volatile("cp.async.commit_group;\n" ::: "memory")
#define CP_WAIT1()  asm volatile("cp.async.wait_group 1;\n" ::: "memory")

// ---------------- elementwise split kernels ----------------
__device__ __forceinline__ void split_body(const float* __restrict__ src,
                                           __half* __restrict__ hi,
                                           __half* __restrict__ lo, int n) {
    int idx = blockIdx.x * blockDim.x + threadIdx.x;
    if (idx < n) {
        float x = src[idx];
        __half h, l; splitf(x, h, l);
        hi[idx] = h; lo[idx] = l;
    }
}
__global__ void __launch_bounds__(256) split_x_kernel(const float* __restrict__ src) {
    split_body(src, g_Xhi, g_Xlo, MROWS*HID);
}
__global__ void __launch_bounds__(256) split_wqkv_kernel(const float* __restrict__ src) {
    split_body(src, g_Wqkvhi, g_Wqkvlo, QKVN*HID);
}
__global__ void __launch_bounds__(256) split_wo_kernel(const float* __restrict__ src) {
    split_body(src, g_Wohi, g_Wolo, HID*HID);
}

// ---------------- RoPE cos/sin table ----------------
__global__ void __launch_bounds__(256) rope_table_kernel() {
    int idx = blockIdx.x * blockDim.x + threadIdx.x;
    if (idx >= SEQ*64) return;
    int i = idx & 63;
    int s = idx >> 6;
    double inv = pow(10000.0, -((double)(2*i)) / 128.0);
    float invf = (float)inv;
    float ang  = (float)s * invf;
    g_cos[idx] = (float)cos((double)ang);
    g_sin[idx] = (float)sin((double)ang);
}

// =====================================================================
//  Pipelined split-fp16 GEMM v2: CTA 256x128, 512 threads, warp 64x32.
//  TERMS=3: AhiBhi + AhiBlo + AloBhi ; TERMS=2: AhiBhi + AhiBlo.
// =====================================================================

#define KC        32
#define GSTAGES   3
#define A_HALF    (256*40)
#define B_HALF    (128*40)
#define STAGE_HALF (2*A_HALF + 2*B_HALF)       /* 30720 */
#define STAGE_BYTES (STAGE_HALF*2)             /* 61440 */
#define GEMM_SMEM (GSTAGES*STAGE_BYTES)        /* 184320 */

static __device__ __forceinline__ void gemm2_load_stage(
    uint32_t stage_base, int tid,
    const __half* __restrict__ Ahi, const __half* __restrict__ Alo,
    const __half* __restrict__ Bhi, const __half* __restrict__ Blo,
    int bm, int bn, int K, int k0)
{
    int chunk = tid & 3;        // 16B chunk within 64B data row
    int r0    = tid >> 2;       // 0..127
    const char* gAh = (const char*)(Ahi + (size_t)bm * K + k0) + chunk * 16;
    const char* gAl = (const char*)(Alo + (size_t)bm * K + k0) + chunk * 16;
    const char* gBh = (const char*)(Bhi + (size_t)bn * K + k0) + chunk * 16;
    const char* gBl = (const char*)(Blo + (size_t)bn * K + k0) + chunk * 16;
    #pragma unroll
    for (int u = 0; u < 2; u++) {
        int row = r0 + u * 128;
        uint32_t so = (uint32_t)(row * 80 + chunk * 16);
        cp_async16(stage_base + so,              gAh + (size_t)row * K * 2);
        cp_async16(stage_base + A_HALF*2 + so,   gAl + (size_t)row * K * 2);
    }
    {
        int row = r0;
        uint32_t so = (uint32_t)(row * 80 + chunk * 16);
        cp_async16(stage_base + 4*A_HALF + so,           gBh + (size_t)row * K * 2);
        cp_async16(stage_base + 4*A_HALF + B_HALF*2 + so, gBl + (size_t)row * K * 2);
    }
}

template<int TERMS>
__global__ void __launch_bounds__(512, 1) gemm_pipe2_kernel(
    const __half* __restrict__ Ahi, const __half* __restrict__ Alo,
    const __half* __restrict__ Bhi, const __half* __restrict__ Blo,
    float* __restrict__ C, int K, int ldc, int grid_m, int grid_n)
{
    extern __shared__ __half smh[];
    uint32_t smem_base = smem_u32(smh);
    int tid = threadIdx.x;
    int wid = tid >> 5;

    // grouped rasterization for L2 reuse
    int pid = blockIdx.x;
    const int GRPW = 8;
    int width = GRPW * grid_n;
    int g   = pid / width;
    int rem = pid - g * width;
    int gm  = grid_m - g * GRPW; if (gm > GRPW) gm = GRPW;
    int bm  = (g * GRPW + (rem % gm)) * 256;
    int bn  = (rem / gm) * 128;

    int wm = (wid >> 2) * 64;   // 4 warp rows of 64
    int wn = (wid & 3) * 32;    // 4 warp cols of 32

    wmma::fragment<wmma::accumulator,16,16,16,float> acc[4][2];
    #pragma unroll
    for (int i = 0; i < 4; i++)
        #pragma unroll
        for (int j = 0; j < 2; j++)
            wmma::fill_fragment(acc[i][j], 0.0f);

    const int NIT = K / KC;

    gemm2_load_stage(smem_base,               tid, Ahi, Alo, Bhi, Blo, bm, bn, K, 0);
    CP_COMMIT();
    gemm2_load_stage(smem_base + STAGE_BYTES, tid, Ahi, Alo, Bhi, Blo, bm, bn, K, KC);
    CP_COMMIT();

    for (int it = 0; it < NIT; it++) {
        CP_WAIT1();
        __syncthreads();

        int nxt = it + 2;
        if (nxt < NIT)
            gemm2_load_stage(smem_base + (uint32_t)(nxt % GSTAGES) * STAGE_BYTES, tid,
                             Ahi, Alo, Bhi, Blo, bm, bn, K, nxt * KC);
        CP_COMMIT();

        const __half* st  = smh + (size_t)(it % GSTAGES) * STAGE_HALF;
        const __half* sAh = st;
        const __half* sAl = st + A_HALF;
        const __half* sBh = st + 2*A_HALF;
        const __half* sBl = st + 2*A_HALF + B_HALF;

        #pragma unroll
        for (int kk = 0; kk < 2; kk++) {
            wmma::fragment<wmma::matrix_a,16,16,16,__half,wmma::row_major> ah[4], al[4];
            #pragma unroll
            for (int i = 0; i < 4; i++) {
                wmma::load_matrix_sync(ah[i], sAh + (wm + i*16)*40 + kk*16, 40);
                if (TERMS == 3)
                    wmma::load_matrix_sync(al[i], sAl + (wm + i*16)*40 + kk*16, 40);
            }
            wmma::fragment<wmma::matrix_b,16,16,16,__half,wmma::col_major> bh[2], bl[2];
            #pragma unroll
            for (int j = 0; j < 2; j++) {
                wmma::load_matrix_sync(bh[j], sBh + (wn + j*16)*40 + kk*16, 40);
                wmma::load_matrix_sync(bl[j], sBl + (wn + j*16)*40 + kk*16, 40);
            }
            #pragma unroll
            for (int i = 0; i < 4; i++)
                #pragma unroll
                for (int j = 0; j < 2; j++) {
                    wmma::mma_sync(acc[i][j], ah[i], bh[j], acc[i][j]);
                    wmma::mma_sync(acc[i][j], ah[i], bl[j], acc[i][j]);
                    if (TERMS == 3)
                        wmma::mma_sync(acc[i][j], al[i], bh[j], acc[i][j]);
                }
        }
        __syncthreads();
    }

    #pragma unroll
    for (int i = 0; i < 4; i++)
        #pragma unroll
        for (int j = 0; j < 2; j++) {
            size_t off = (size_t)(bm + wm + i*16) * ldc + bn + wn + j*16;
            wmma::store_matrix_sync(&C[off], acc[i][j], ldc, wmma::mem_row_major);
        }
}

// ---------------- RoPE + transpose to [B,NH,S,D], split to hi/lo ----------------
__global__ void __launch_bounds__(256) rope_transpose_kernel() {
    int idx = blockIdx.x * blockDim.x + threadIdx.x;
    if (idx >= BATCH*SEQ*NHEAD*64) return;
    int i = idx & 63;
    int h = (idx >> 6) & 31;
    int s = (idx >> 11) & 2047;
    int b = idx >> 22;

    size_t row  = (size_t)b * SEQ + s;
    size_t base = row * QKVN + (size_t)h * HDIM;

    float q1 = g_qkv[base + i],         q2 = g_qkv[base + i + 64];
    float k1 = g_qkv[base + HID + i],   k2 = g_qkv[base + HID + i + 64];
    float v1 = g_qkv[base + 2*HID + i], v2 = g_qkv[base + 2*HID + i + 64];

    float c  = g_cos[s*64 + i];
    float sn = g_sin[s*64 + i];

    size_t dst = (((size_t)b * NHEAD + h) * SEQ + s) * HDIM + i;

    __half hi, lo;
    splitf(q1*c - q2*sn, hi, lo); g_Qhi[dst]     = hi; g_Qlo[dst]     = lo;
    splitf(q1*sn + q2*c, hi, lo); g_Qhi[dst+64]  = hi; g_Qlo[dst+64]  = lo;
    splitf(k1*c - k2*sn, hi, lo); g_Khi[dst]     = hi; g_Klo[dst]     = lo;
    splitf(k1*sn + k2*c, hi, lo); g_Khi[dst+64]  = hi; g_Klo[dst+64]  = lo;
    g_V[dst]    = __float2half(v1);
    g_V[dst+64] = __float2half(v2);
}

// ---------------- flash attention (unchanged from R3) ----------------
#define TILE_H   (64*136)
#define TILE_B   (TILE_H*2)
#define FL_SMEM  (8*TILE_B + 64*68*4 + 64*72*2 + 64*132*4 + 3*64*4)

static __device__ __forceinline__ void flash_issue_tile(
    uint32_t dKh, uint32_t dKl, uint32_t dV,
    const __half* __restrict__ Kh, const __half* __restrict__ Kl,
    const __half* __restrict__ V, int tid)
{
    int chunk = tid & 15;
    int r0    = tid >> 4;
    #pragma unroll
    for (int u = 0; u < 4; u++) {
        int r = r0 + u * 16;
        uint32_t so = (uint32_t)(r * 272 + chunk * 16);
        size_t   go = (size_t)r * HDIM * 2 + chunk * 16;
        cp_async16(dKh + so, (const char*)Kh + go);
        cp_async16(dKl + so, (const char*)Kl + go);
        cp_async16(dV  + so, (const char*)V  + go);
    }
}

__global__ void __launch_bounds__(256) flash_kernel() {
    extern __shared__ unsigned char smraw[];
    __half* sQh = (__half*)smraw;
    __half* sQl = sQh + TILE_H;
    __half* sKB = sQl + TILE_H;
    float*  sS  = (float*)(sKB + 6*TILE_H);
    __half* sP  = (__half*)(sS + 64*68);
    float*  sO  = (float*)(sP + 64*72);
    float*  smx = sO + 64*132;
    float*  sl  = smx + 64;
    float*  sal = sl + 64;

    int tid = threadIdx.x;
    int wid = tid >> 5;
    int qt  = blockIdx.x;
    int h   = blockIdx.y;
    int b   = blockIdx.z;
    int bh  = b * NHEAD + h;
    int q0  = qt * 64;

    const float scale = 0.08838834764831845f;

    const __half* Khg = g_Khi + (size_t)bh * SEQ * HDIM;
    const __half* Klg = g_Klo + (size_t)bh * SEQ * HDIM;
    const __half* Vg  = g_V   + (size_t)bh * SEQ * HDIM;

    uint32_t sKB_u = smem_u32(sKB);

    flash_issue_tile(sKB_u, sKB_u + TILE_B, sKB_u + 2*TILE_B, Khg, Klg, Vg, tid);
    CP_COMMIT();

    {
        const __half* Qh = g_Qhi + ((size_t)bh * SEQ + q0) * HDIM;
        const __half* Ql = g_Qlo + ((size_t)bh * SEQ + q0) * HDIM;
        for (int v = tid; v < 1024; v += 256) {
            int r = v >> 4, c = (v & 15) << 3;
            *(int4*)(sQh + r*136 + c) = *(const int4*)(Qh + r*HDIM + c);
            *(int4*)(sQl + r*136 + c) = *(const int4*)(Ql + r*HDIM + c);
        }
    }
    for (int v = tid; v < 64*132; v += 256) sO[v] = 0.0f;
    if (tid < 64) { smx[tid] = -INFINITY; sl[tid] = 0.0f; }

    int wm = (wid >> 1) * 16;

    for (int kt = 0; kt <= qt; kt++) {
        if (kt + 1 <= qt) {
            uint32_t nb = sKB_u + (uint32_t)((kt + 1) & 1) * 3 * TILE_B;
            flash_issue_tile(nb, nb + TILE_B, nb + 2*TILE_B,
                             Khg + (size_t)(kt+1)*64*HDIM,
                             Klg + (size_t)(kt+1)*64*HDIM,
                             Vg  + (size_t)(kt+1)*64*HDIM, tid);
        }
        CP_COMMIT();
        CP_WAIT1();
        __syncthreads();

        __half* sKh = sKB + (size_t)(kt & 1) * 3 * TILE_H;
        __half* sKl = sKh + TILE_H;
        __half* sV  = sKh + 2*TILE_H;

        {
            int wn = (wid & 1) * 32;
            wmma::fragment<wmma::accumulator,16,16,16,float> sacc[2];
            wmma::fill_fragment(sacc[0], 0.0f);
            wmma::fill_fragment(sacc[1], 0.0f);
            #pragma unroll
            for (int d8 = 0; d8 < 8; d8++) {
                wmma::fragment<wmma::matrix_a,16,16,16,__half,wmma::row_major> ah, al;
                wmma::load_matrix_sync(ah, sQh + wm*136 + d8*16, 136);
                wmma::load_matrix_sync(al, sQl + wm*136 + d8*16, 136);
                #pragma unroll
                for (int j = 0; j < 2; j++) {
                    wmma::fragment<wmma::matrix_b,16,16,16,__half,wmma::col_major> kh, kl;
                    wmma::load_matrix_sync(kh, sKh + (wn + j*16)*136 + d8*16, 136);
                    wmma::load_matrix_sync(kl, sKl + (wn + j*16)*136 + d8*16, 136);
                    wmma::mma_sync(sacc[j], ah, kh, sacc[j]);
                    wmma::mma_sync(sacc[j], ah, kl, sacc[j]);
                    wmma::mma_sync(sacc[j], al, kh, sacc[j]);
                }
            }
            wmma::store_matrix_sync(sS + wm*68 + wn,      sacc[0], 68, wmma::mem_row_major);
            wmma::store_matrix_sync(sS + wm*68 + wn + 16, sacc[1], 68, wmma::mem_row_major);
        }
        __syncthreads();

        {
            int r    = tid >> 2;
            int lane = tid & 3;
            bool diag = (kt == qt);
            int jmax = diag ? (r + 1) : 64;

            float lm = -INFINITY;
            #pragma unroll
            for (int jj = 0; jj < 16; jj++) {
                int j = lane*16 + jj;
                if (j < jmax) lm = fmaxf(lm, sS[r*68 + j] * scale);
            }
            lm = fmaxf(lm, __shfl_xor_sync(0xffffffffu, lm, 1));
            lm = fmaxf(lm, __shfl_xor_sync(0xffffffffu, lm, 2));
            float mo = smx[r];
            float mn = fmaxf(mo, lm);

            float rl = 0.0f;
            #pragma unroll
            for (int jj = 0; jj < 16; jj++) {
                int j = lane*16 + jj;
                float p = 0.0f;
                if (j < jmax) { p = expf(sS[r*68 + j] * scale - mn); rl += p; }
                sP[r*72 + j] = __float2half(p);
            }
            rl += __shfl_xor_sync(0xffffffffu, rl, 1);
            rl += __shfl_xor_sync(0xffffffffu, rl, 2);

            if (lane == 0) {
                float a = expf(mo - mn);
                sal[r] = a;
                smx[r] = mn;
                sl[r]  = sl[r] * a + rl;
            }
        }
        __syncthreads();

        for (int v = tid; v < 64*128; v += 256) {
            int r = v >> 7, d = v & 127;
            sO[r*132 + d] *= sal[r];
        }
        __syncthreads();

        {
            int wn2 = (wid & 1) * 64;
            wmma::fragment<wmma::accumulator,16,16,16,float> oc[4];
            #pragma unroll
            for (int j = 0; j < 4; j++)
                wmma::load_matrix_sync(oc[j], sO + wm*132 + wn2 + j*16, 132, wmma::mem_row_major);
            #pragma unroll
            for (int kk = 0; kk < 4; kk++) {
                wmma::fragment<wmma::matrix_a,16,16,16,__half,wmma::row_major> pf;
                wmma::load_matrix_sync(pf, sP + wm*72 + kk*16, 72);
                #pragma unroll
                for (int j = 0; j < 4; j++) {
                    wmma::fragment<wmma::matrix_b,16,16,16,__half,wmma::row_major> vf;
                    wmma::load_matrix_sync(vf, sV + (kk*16)*136 + wn2 + j*16, 136);
                    wmma::mma_sync(oc[j], pf, vf, oc[j]);
                }
            }
            #pragma unroll
            for (int j = 0; j < 4; j++)
                wmma::store_matrix_sync(sO + wm*132 + wn2 + j*16, oc[j], 132, wmma::mem_row_major);
        }
        __syncthreads();
    }

    for (int v = tid; v < 64*128; v += 256) {
        int r = v >> 7, d = v & 127;
        float o = sO[r*132 + d] / sl[r];
        size_t dst = ((size_t)b * SEQ + q0 + r) * HID + (size_t)h * HDIM + d;
        __half hi, lo; splitf(o, hi, lo);
        g_AOhi[dst] = hi; g_AOlo[dst] = lo;
    }
}

// ---------------- launch ----------------
extern "C" void kernel_launch(void* const* d_in, const int* in_sizes, int n_in,
                              void* d_out, int out_size) {
    const float* X    = (const float*)d_in[0];
    const float* Wqkv = (const float*)d_in[1];
    const float* Wo   = (const float*)d_in[2];

    cudaFuncSetAttribute(flash_kernel, cudaFuncAttributeMaxDynamicSharedMemorySize, FL_SMEM);
    cudaFuncSetAttribute(gemm_pipe2_kernel<3>, cudaFuncAttributeMaxDynamicSharedMemorySize, GEMM_SMEM);
    cudaFuncSetAttribute(gemm_pipe2_kernel<2>, cudaFuncAttributeMaxDynamicSharedMemorySize, GEMM_SMEM);

    __half *Xhi, *Xlo, *Wqh, *Wql, *Woh, *Wol, *AOh, *AOl;
    float  *qkv;
    cudaGetSymbolAddress((void**)&Xhi, g_Xhi);
    cudaGetSymbolAddress((void**)&Xlo, g_Xlo);
    cudaGetSymbolAddress((void**)&Wqh, g_Wqkvhi);
    cudaGetSymbolAddress((void**)&Wql, g_Wqkvlo);
    cudaGetSymbolAddress((void**)&Woh, g_Wohi);
    cudaGetSymbolAddress((void**)&Wol, g_Wolo);
    cudaGetSymbolAddress((void**)&AOh, g_AOhi);
    cudaGetSymbolAddress((void**)&AOl, g_AOlo);
    cudaGetSymbolAddress((void**)&qkv, g_qkv);

    split_x_kernel   <<<(MROWS*HID + 255)/256, 256>>>(X);
    split_wqkv_kernel<<<(QKVN*HID  + 255)/256, 256>>>(Wqkv);
    split_wo_kernel  <<<(HID*HID   + 255)/256, 256>>>(Wo);
    rope_table_kernel<<<(SEQ*64    + 255)/256, 256>>>();

    // QKV projection, Q+K columns (N=8192): 3-term (softmax-amplified path)
    gemm_pipe2_kernel<3><<<(MROWS/256)*(2*HID/128), 512, GEMM_SMEM>>>(
        Xhi, Xlo, Wqh, Wql, qkv, HID, QKVN, MROWS/256, 2*HID/128);

    // QKV projection, V columns (N=4096): 2-term (linear path)
    gemm_pipe2_kernel<2><<<(MROWS/256)*(HID/128), 512, GEMM_SMEM>>>(
        Xhi, Xlo, Wqh + (size_t)2*HID*HID, Wql + (size_t)2*HID*HID,
        qkv + 2*HID, HID, QKVN, MROWS/256, HID/128);

    rope_transpose_kernel<<<(BATCH*SEQ*NHEAD*64 + 255)/256, 256>>>();

    flash_kernel<<<dim3(SEQ/64, NHEAD, BATCH), 256, FL_SMEM>>>();

    // Output projection (N=4096): 2-term (linear path)
    gemm_pipe2_kernel<2><<<(MROWS/256)*(HID/128), 512, GEMM_SMEM>>>(
        AOh, AOl, Woh, Wol, (float*)d_out, HID, HID, MROWS/256, HID/128);
}

// round 5
// speedup vs baseline: 1.7243x; 1.0745x over previous
#include <cuda_runtime.h>
#include <cuda_fp16.h>
#include <mma.h>
#include <math.h>
#include <stdint.h>

using namespace nvcuda;

#define BATCH 2
#define SEQ   2048
#define HID   4096
#define NHEAD 32
#define HDIM  128
#define MROWS (BATCH*SEQ)     /* 4096 */
#define QKVN  (3*HID)         /* 12288 */

// ---------------- scratch ----------------
__device__ __half g_Xhi   [MROWS*HID];
__device__ __half g_Xlo   [MROWS*HID];
__device__ __half g_Wqkvhi[QKVN*HID];
__device__ __half g_Wqkvlo[QKVN*HID];
__device__ __half g_Wohi  [HID*HID];
__device__ __half g_Wolo  [HID*HID];
__device__ __half g_Qhi   [MROWS*HID];
__device__ __half g_Qlo   [MROWS*HID];
__device__ __half g_Khi   [MROWS*HID];
__device__ __half g_Klo   [MROWS*HID];
__device__ __half g_V     [MROWS*HID];
__device__ __half g_AOhi  [MROWS*HID];
__device__ __half g_AOlo  [MROWS*HID];
__device__ float  g_cos   [SEQ*64];
__device__ float  g_sin   [SEQ*64];

__device__ __forceinline__ void splitf(float x, __half &hi, __half &lo) {
    hi = __float2half(x);
    lo = __float2half(x - __half2float(hi));
}

// ---------------- cp.async helpers ----------------
static __device__ __forceinline__ uint32_t smem_u32(const void* p) {
    uint32_t a;
    asm("{ .reg .u64 t; cvta.to.shared.u64 t, %1; cvt.u32.u64 %0, t; }" : "=r"(a) : "l"(p));
    return a;
}
static __device__ __forceinline__ void cp_async16(uint32_t dst, const void* src) {
    asm volatile("cp.async.cg.shared.global [%0], [%1], 16;\n" :: "r"(dst), "l"(src));
}
#define CP_COMMIT() asm volatile("cp.async.commit_group;\n" ::: "memory")
#define CP_WAIT1()  asm volatile("cp.async.wait_group 1;\n" ::: "memory")

// ---------------- elementwise split kernels ----------------
__device__ __forceinline__ void split_body(const float* __restrict__ src,
                                           __half* __restrict__ hi,
                                           __half* __restrict__ lo, int n) {
    int idx = blockIdx.x * blockDim.x + threadIdx.x;
    if (idx < n) {
        float x = src[idx];
        __half h, l; splitf(x, h, l);
        hi[idx] = h; lo[idx] = l;
    }
}
__global__ void __launch_bounds__(256) split_x_kernel(const float* __restrict__ src) {
    split_body(src, g_Xhi, g_Xlo, MROWS*HID);
}
__global__ void __launch_bounds__(256) split_wqkv_kernel(const float* __restrict__ src) {
    split_body(src, g_Wqkvhi, g_Wqkvlo, QKVN*HID);
}
__global__ void __launch_bounds__(256) split_wo_kernel(const float* __restrict__ src) {
    split_body(src, g_Wohi, g_Wolo, HID*HID);
}

// ---------------- RoPE cos/sin table ----------------
__global__ void __launch_bounds__(256) rope_table_kernel() {
    int idx = blockIdx.x * blockDim.x + threadIdx.x;
    if (idx >= SEQ*64) return;
    int i = idx & 63;
    int s = idx >> 6;
    double inv = pow(10000.0, -((double)(2*i)) / 128.0);
    float invf = (float)inv;
    float ang  = (float)s * invf;
    g_cos[idx] = (float)cos((double)ang);
    g_sin[idx] = (float)sin((double)ang);
}

// =====================================================================
//  Pipelined split-fp16 GEMM v3: CTA 256x128, 512 threads, warp 64x32.
//  KC=64, 2-stage cp.async. TERMS: 3 or 2 split terms.
//  EPI: 0 = fp32 C direct ; 1 = fused RoPE+transpose+split (Q/K) ;
//       2 = direct fp16 V transpose.
// =====================================================================

#define KC        64
#define GSTAGES   2
#define A_HALF    (256*72)                 /* 64 data halves + 8 pad */
#define B_HALF    (128*72)
#define STAGE_HALF (2*A_HALF + 2*B_HALF)   /* 55296 */
#define STAGE_BYTES (STAGE_HALF*2)         /* 110592 */
#define GEMM_SMEM (GSTAGES*STAGE_BYTES)    /* 221184 */

static __device__ __forceinline__ void gemm3_load_stage(
    uint32_t stage_base, int tid,
    const __half* __restrict__ Ahi, const __half* __restrict__ Alo,
    const __half* __restrict__ Bhi, const __half* __restrict__ Blo,
    int bm, int bn, int K, int k0)
{
    int chunk = tid & 7;        // 16B chunk within 128B data row
    int r0    = tid >> 3;       // 0..63
    const char* gAh = (const char*)(Ahi + (size_t)bm * K + k0) + chunk * 16;
    const char* gAl = (const char*)(Alo + (size_t)bm * K + k0) + chunk * 16;
    const char* gBh = (const char*)(Bhi + (size_t)bn * K + k0) + chunk * 16;
    const char* gBl = (const char*)(Blo + (size_t)bn * K + k0) + chunk * 16;
    #pragma unroll
    for (int u = 0; u < 4; u++) {
        int row = r0 + u * 64;
        uint32_t so = (uint32_t)(row * 144 + chunk * 16);
        cp_async16(stage_base + so,              gAh + (size_t)row * K * 2);
        cp_async16(stage_base + 2*A_HALF + so,   gAl + (size_t)row * K * 2);
    }
    #pragma unroll
    for (int u = 0; u < 2; u++) {
        int row = r0 + u * 64;
        uint32_t so = (uint32_t)(row * 144 + chunk * 16);
        cp_async16(stage_base + 4*A_HALF + so,             gBh + (size_t)row * K * 2);
        cp_async16(stage_base + 4*A_HALF + 2*B_HALF + so,  gBl + (size_t)row * K * 2);
    }
}

template<int TERMS, int EPI>
__global__ void __launch_bounds__(512, 1) gemm_pipe3_kernel(
    const __half* __restrict__ Ahi, const __half* __restrict__ Alo,
    const __half* __restrict__ Bhi, const __half* __restrict__ Blo,
    float* __restrict__ C, int K, int ldc, int grid_m, int grid_n)
{
    extern __shared__ __half smh[];
    uint32_t smem_base = smem_u32(smh);
    int tid = threadIdx.x;
    int wid = tid >> 5;

    // grouped rasterization for L2 reuse
    int pid = blockIdx.x;
    const int GRPW = 8;
    int width = GRPW * grid_n;
    int g   = pid / width;
    int rem = pid - g * width;
    int gm  = grid_m - g * GRPW; if (gm > GRPW) gm = GRPW;
    int bm  = (g * GRPW + (rem % gm)) * 256;
    int bn  = (rem / gm) * 128;

    int wm = (wid >> 2) * 64;   // 4 warp rows of 64
    int wn = (wid & 3) * 32;    // 4 warp cols of 32

    wmma::fragment<wmma::accumulator,16,16,16,float> acc[4][2];
    #pragma unroll
    for (int i = 0; i < 4; i++)
        #pragma unroll
        for (int j = 0; j < 2; j++)
            wmma::fill_fragment(acc[i][j], 0.0f);

    const int NIT = K / KC;

    gemm3_load_stage(smem_base,               tid, Ahi, Alo, Bhi, Blo, bm, bn, K, 0);
    CP_COMMIT();
    gemm3_load_stage(smem_base + STAGE_BYTES, tid, Ahi, Alo, Bhi, Blo, bm, bn, K, KC);
    CP_COMMIT();

    for (int it = 0; it < NIT; it++) {
        CP_WAIT1();
        __syncthreads();

        const __half* st  = smh + (size_t)(it & 1) * STAGE_HALF;
        const __half* sAh = st;
        const __half* sAl = st + A_HALF;
        const __half* sBh = st + 2*A_HALF;
        const __half* sBl = st + 2*A_HALF + B_HALF;

        #pragma unroll
        for (int kk = 0; kk < 4; kk++) {
            wmma::fragment<wmma::matrix_b,16,16,16,__half,wmma::col_major> bh[2], bl[2];
            #pragma unroll
            for (int j = 0; j < 2; j++) {
                wmma::load_matrix_sync(bh[j], sBh + (wn + j*16)*72 + kk*16, 72);
                wmma::load_matrix_sync(bl[j], sBl + (wn + j*16)*72 + kk*16, 72);
            }
            #pragma unroll
            for (int i = 0; i < 4; i++) {
                wmma::fragment<wmma::matrix_a,16,16,16,__half,wmma::row_major> ah, al;
                wmma::load_matrix_sync(ah, sAh + (wm + i*16)*72 + kk*16, 72);
                if (TERMS == 3)
                    wmma::load_matrix_sync(al, sAl + (wm + i*16)*72 + kk*16, 72);
                #pragma unroll
                for (int j = 0; j < 2; j++) {
                    wmma::mma_sync(acc[i][j], ah, bh[j], acc[i][j]);
                    wmma::mma_sync(acc[i][j], ah, bl[j], acc[i][j]);
                    if (TERMS == 3)
                        wmma::mma_sync(acc[i][j], al, bh[j], acc[i][j]);
                }
            }
        }
        __syncthreads();

        int nxt = it + 2;
        if (nxt < NIT)
            gemm3_load_stage(smem_base + (uint32_t)(nxt & 1) * STAGE_BYTES, tid,
                             Ahi, Alo, Bhi, Blo, bm, bn, K, nxt * KC);
        CP_COMMIT();
    }

    if (EPI == 0) {
        // direct fp32 store
        #pragma unroll
        for (int i = 0; i < 4; i++)
            #pragma unroll
            for (int j = 0; j < 2; j++) {
                size_t off = (size_t)(bm + wm + i*16) * ldc + bn + wn + j*16;
                wmma::store_matrix_sync(&C[off], acc[i][j], ldc, wmma::mem_row_major);
            }
        return;
    }

    // stage C tile (256 x 128, stride 132) in smem for fused epilogue
    float* sC = (float*)smh;
    #pragma unroll
    for (int i = 0; i < 4; i++)
        #pragma unroll
        for (int j = 0; j < 2; j++)
            wmma::store_matrix_sync(sC + (wm + i*16)*132 + wn + j*16, acc[i][j],
                                    132, wmma::mem_row_major);
    __syncthreads();

    if (EPI == 1) {
        // RoPE + transpose + hi/lo split.  bn in [0,8192): Q cols [0,HID), K cols [HID,2*HID)
        bool isk = (bn >= HID);
        int h = (bn & (HID-1)) >> 7;
        __half* Dh = isk ? g_Khi : g_Qhi;
        __half* Dl = isk ? g_Klo : g_Qlo;
        for (int idx = tid; idx < 256*64; idx += 512) {
            int r = idx >> 6, d = idx & 63;
            float x1 = sC[r*132 + d];
            float x2 = sC[r*132 + d + 64];
            int row = bm + r;
            int s   = row & (SEQ-1);
            int b   = row >> 11;
            float c  = g_cos[s*64 + d];
            float sn = g_sin[s*64 + d];
            float o1 = x1*c - x2*sn;
            float o2 = x1*sn + x2*c;
            size_t dst = (((size_t)b * NHEAD + h) * SEQ + s) * HDIM + d;
            __half hi, lo;
            splitf(o1, hi, lo); Dh[dst]    = hi; Dl[dst]    = lo;
            splitf(o2, hi, lo); Dh[dst+64] = hi; Dl[dst+64] = lo;
        }
    } else {
        // EPI == 2: V, direct fp16 transpose write. bn in [0,4096)
        int h = bn >> 7;
        for (int idx = tid; idx < 256*128; idx += 512) {
            int r = idx >> 7, d = idx & 127;
            int row = bm + r;
            int s   = row & (SEQ-1);
            int b   = row >> 11;
            g_V[(((size_t)b * NHEAD + h) * SEQ + s) * HDIM + d] = __float2half(sC[r*132 + d]);
        }
    }
}

// ---------------- flash attention, 64-row q tiles, causal, cp.async double buffer ----------------
#define TILE_H   (64*136)
#define TILE_B   (TILE_H*2)
#define FL_SMEM  (8*TILE_B + 64*68*4 + 64*72*2 + 64*132*4 + 3*64*4)

static __device__ __forceinline__ void flash_issue_tile(
    uint32_t dKh, uint32_t dKl, uint32_t dV,
    const __half* __restrict__ Kh, const __half* __restrict__ Kl,
    const __half* __restrict__ V, int tid)
{
    int chunk = tid & 15;
    int r0    = tid >> 4;
    #pragma unroll
    for (int u = 0; u < 4; u++) {
        int r = r0 + u * 16;
        uint32_t so = (uint32_t)(r * 272 + chunk * 16);
        size_t   go = (size_t)r * HDIM * 2 + chunk * 16;
        cp_async16(dKh + so, (const char*)Kh + go);
        cp_async16(dKl + so, (const char*)Kl + go);
        cp_async16(dV  + so, (const char*)V  + go);
    }
}

__global__ void __launch_bounds__(256) flash_kernel() {
    extern __shared__ unsigned char smraw[];
    __half* sQh = (__half*)smraw;
    __half* sQl = sQh + TILE_H;
    __half* sKB = sQl + TILE_H;
    float*  sS  = (float*)(sKB + 6*TILE_H);
    __half* sP  = (__half*)(sS + 64*68);
    float*  sO  = (float*)(sP + 64*72);
    float*  smx = sO + 64*132;
    float*  sl  = smx + 64;
    float*  sal = sl + 64;

    int tid = threadIdx.x;
    int wid = tid >> 5;
    int qt  = gridDim.x - 1 - blockIdx.x;   // longest CTAs first
    int h   = blockIdx.y;
    int b   = blockIdx.z;
    int bh  = b * NHEAD + h;
    int q0  = qt * 64;

    const float scale = 0.08838834764831845f;

    const __half* Khg = g_Khi + (size_t)bh * SEQ * HDIM;
    const __half* Klg = g_Klo + (size_t)bh * SEQ * HDIM;
    const __half* Vg  = g_V   + (size_t)bh * SEQ * HDIM;

    uint32_t sKB_u = smem_u32(sKB);

    flash_issue_tile(sKB_u, sKB_u + TILE_B, sKB_u + 2*TILE_B, Khg, Klg, Vg, tid);
    CP_COMMIT();

    {
        const __half* Qh = g_Qhi + ((size_t)bh * SEQ + q0) * HDIM;
        const __half* Ql = g_Qlo + ((size_t)bh * SEQ + q0) * HDIM;
        for (int v = tid; v < 1024; v += 256) {
            int r = v >> 4, c = (v & 15) << 3;
            *(int4*)(sQh + r*136 + c) = *(const int4*)(Qh + r*HDIM + c);
            *(int4*)(sQl + r*136 + c) = *(const int4*)(Ql + r*HDIM + c);
        }
    }
    for (int v = tid; v < 64*132; v += 256) sO[v] = 0.0f;
    if (tid < 64) { smx[tid] = -INFINITY; sl[tid] = 0.0f; }

    int wm = (wid >> 1) * 16;

    for (int kt = 0; kt <= qt; kt++) {
        if (kt + 1 <= qt) {
            uint32_t nb = sKB_u + (uint32_t)((kt + 1) & 1) * 3 * TILE_B;
            flash_issue_tile(nb, nb + TILE_B, nb + 2*TILE_B,
                             Khg + (size_t)(kt+1)*64*HDIM,
                             Klg + (size_t)(kt+1)*64*HDIM,
                             Vg  + (size_t)(kt+1)*64*HDIM, tid);
        }
        CP_COMMIT();
        CP_WAIT1();
        __syncthreads();

        __half* sKh = sKB + (size_t)(kt & 1) * 3 * TILE_H;
        __half* sKl = sKh + TILE_H;
        __half* sV  = sKh + 2*TILE_H;

        {
            int wn = (wid & 1) * 32;
            wmma::fragment<wmma::accumulator,16,16,16,float> sacc[2];
            wmma::fill_fragment(sacc[0], 0.0f);
            wmma::fill_fragment(sacc[1], 0.0f);
            #pragma unroll
            for (int d8 = 0; d8 < 8; d8++) {
                wmma::fragment<wmma::matrix_a,16,16,16,__half,wmma::row_major> ah, al;
                wmma::load_matrix_sync(ah, sQh + wm*136 + d8*16, 136);
                wmma::load_matrix_sync(al, sQl + wm*136 + d8*16, 136);
                #pragma unroll
                for (int j = 0; j < 2; j++) {
                    wmma::fragment<wmma::matrix_b,16,16,16,__half,wmma::col_major> kh, kl;
                    wmma::load_matrix_sync(kh, sKh + (wn + j*16)*136 + d8*16, 136);
                    wmma::load_matrix_sync(kl, sKl + (wn + j*16)*136 + d8*16, 136);
                    wmma::mma_sync(sacc[j], ah, kh, sacc[j]);
                    wmma::mma_sync(sacc[j], ah, kl, sacc[j]);
                    wmma::mma_sync(sacc[j], al, kh, sacc[j]);
                }
            }
            wmma::store_matrix_sync(sS + wm*68 + wn,      sacc[0], 68, wmma::mem_row_major);
            wmma::store_matrix_sync(sS + wm*68 + wn + 16, sacc[1], 68, wmma::mem_row_major);
        }
        __syncthreads();

        {
            int r    = tid >> 2;
            int lane = tid & 3;
            bool diag = (kt == qt);
            int jmax = diag ? (r + 1) : 64;

            float lm = -INFINITY;
            #pragma unroll
            for (int jj = 0; jj < 16; jj++) {
                int j = lane*16 + jj;
                if (j < jmax) lm = fmaxf(lm, sS[r*68 + j] * scale);
            }
            lm = fmaxf(lm, __shfl_xor_sync(0xffffffffu, lm, 1));
            lm = fmaxf(lm, __shfl_xor_sync(0xffffffffu, lm, 2));
            float mo = smx[r];
            float mn = fmaxf(mo, lm);

            float rl = 0.0f;
            #pragma unroll
            for (int jj = 0; jj < 16; jj++) {
                int j = lane*16 + jj;
                float p = 0.0f;
                if (j < jmax) { p = expf(sS[r*68 + j] * scale - mn); rl += p; }
                sP[r*72 + j] = __float2half(p);
            }
            rl += __shfl_xor_sync(0xffffffffu, rl, 1);
            rl += __shfl_xor_sync(0xffffffffu, rl, 2);

            if (lane == 0) {
                float a = expf(mo - mn);
                sal[r] = a;
                smx[r] = mn;
                sl[r]  = sl[r] * a + rl;
            }
        }
        __syncthreads();

        for (int v = tid; v < 64*128; v += 256) {
            int r = v >> 7, d = v & 127;
            sO[r*132 + d] *= sal[r];
        }
        __syncthreads();

        {
            int wn2 = (wid & 1) * 64;
            wmma::fragment<wmma::accumulator,16,16,16,float> oc[4];
            #pragma unroll
            for (int j = 0; j < 4; j++)
                wmma::load_matrix_sync(oc[j], sO + wm*132 + wn2 + j*16, 132, wmma::mem_row_major);
            #pragma unroll
            for (int kk = 0; kk < 4; kk++) {
                wmma::fragment<wmma::matrix_a,16,16,16,__half,wmma::row_major> pf;
                wmma::load_matrix_sync(pf, sP + wm*72 + kk*16, 72);
                #pragma unroll
                for (int j = 0; j < 4; j++) {
                    wmma::fragment<wmma::matrix_b,16,16,16,__half,wmma::row_major> vf;
                    wmma::load_matrix_sync(vf, sV + (kk*16)*136 + wn2 + j*16, 136);
                    wmma::mma_sync(oc[j], pf, vf, oc[j]);
                }
            }
            #pragma unroll
            for (int j = 0; j < 4; j++)
                wmma::store_matrix_sync(sO + wm*132 + wn2 + j*16, oc[j], 132, wmma::mem_row_major);
        }
        __syncthreads();
    }

    for (int v = tid; v < 64*128; v += 256) {
        int r = v >> 7, d = v & 127;
        float o = sO[r*132 + d] / sl[r];
        size_t dst = ((size_t)b * SEQ + q0 + r) * HID + (size_t)h * HDIM + d;
        __half hi, lo; splitf(o, hi, lo);
        g_AOhi[dst] = hi; g_AOlo[dst] = lo;
    }
}

// ---------------- launch ----------------
extern "C" void kernel_launch(void* const* d_in, const int* in_sizes, int n_in,
                              void* d_out, int out_size) {
    const float* X    = (const float*)d_in[0];
    const float* Wqkv = (const float*)d_in[1];
    const float* Wo   = (const float*)d_in[2];

    cudaFuncSetAttribute(flash_kernel, cudaFuncAttributeMaxDynamicSharedMemorySize, FL_SMEM);
    cudaFuncSetAttribute(gemm_pipe3_kernel<3,1>, cudaFuncAttributeMaxDynamicSharedMemorySize, GEMM_SMEM);
    cudaFuncSetAttribute(gemm_pipe3_kernel<2,2>, cudaFuncAttributeMaxDynamicSharedMemorySize, GEMM_SMEM);
    cudaFuncSetAttribute(gemm_pipe3_kernel<2,0>, cudaFuncAttributeMaxDynamicSharedMemorySize, GEMM_SMEM);

    __half *Xhi, *Xlo, *Wqh, *Wql, *Woh, *Wol, *AOh, *AOl;
    cudaGetSymbolAddress((void**)&Xhi, g_Xhi);
    cudaGetSymbolAddress((void**)&Xlo, g_Xlo);
    cudaGetSymbolAddress((void**)&Wqh, g_Wqkvhi);
    cudaGetSymbolAddress((void**)&Wql, g_Wqkvlo);
    cudaGetSymbolAddress((void**)&Woh, g_Wohi);
    cudaGetSymbolAddress((void**)&Wol, g_Wolo);
    cudaGetSymbolAddress((void**)&AOh, g_AOhi);
    cudaGetSymbolAddress((void**)&AOl, g_AOlo);

    split_x_kernel   <<<(MROWS*HID + 255)/256, 256>>>(X);
    split_wqkv_kernel<<<(QKVN*HID  + 255)/256, 256>>>(Wqkv);
    split_wo_kernel  <<<(HID*HID   + 255)/256, 256>>>(Wo);
    rope_table_kernel<<<(SEQ*64    + 255)/256, 256>>>();

    // Q+K projection (N=8192): 3-term, fused RoPE/transpose/split epilogue
    gemm_pipe3_kernel<3,1><<<(MROWS/256)*(2*HID/128), 512, GEMM_SMEM>>>(
        Xhi, Xlo, Wqh, Wql, nullptr, HID, 0, MROWS/256, 2*HID/128);

    // V projection (N=4096): 2-term, direct fp16 transpose epilogue
    gemm_pipe3_kernel<2,2><<<(MROWS/256)*(HID/128), 512, GEMM_SMEM>>>(
        Xhi, Xlo, Wqh + (size_t)2*HID*HID, Wql + (size_t)2*HID*HID,
        nullptr, HID, 0, MROWS/256, HID/128);

    flash_kernel<<<dim3(SEQ/64, NHEAD, BATCH), 256, FL_SMEM>>>();

    // Output projection (N=4096): 2-term, direct fp32 store
    gemm_pipe3_kernel<2,0><<<(MROWS/256)*(HID/128), 512, GEMM_SMEM>>>(
        AOh, AOl, Woh, Wol, (float*)d_out, HID, HID, MROWS/256, HID/128);
}

// round 6
// speedup vs baseline: 1.7327x; 1.0049x over previous
#include <cuda_runtime.h>
#include <cuda_fp16.h>
#include <mma.h>
#include <math.h>
#include <stdint.h>

using namespace nvcuda;

#define BATCH 2
#define SEQ   2048
#define HID   4096
#define NHEAD 32
#define HDIM  128
#define MROWS (BATCH*SEQ)     /* 4096 */
#define QKVN  (3*HID)         /* 12288 */

// ---------------- scratch ----------------
__device__ __half g_Xhi   [MROWS*HID];
__device__ __half g_Xlo   [MROWS*HID];
__device__ __half g_Wqkvhi[QKVN*HID];
__device__ __half g_Wqkvlo[QKVN*HID];
__device__ __half g_Wohi  [HID*HID];
__device__ __half g_Wolo  [HID*HID];
__device__ __half g_Qhi   [MROWS*HID];
__device__ __half g_Qlo   [MROWS*HID];
__device__ __half g_Khi   [MROWS*HID];
__device__ __half g_Klo   [MROWS*HID];
__device__ __half g_V     [MROWS*HID];
__device__ __half g_AOhi  [MROWS*HID];
__device__ __half g_AOlo  [MROWS*HID];
__device__ float  g_cos   [SEQ*64];
__device__ float  g_sin   [SEQ*64];

__device__ __forceinline__ void splitf(float x, __half &hi, __half &lo) {
    hi = __float2half(x);
    lo = __float2half(x - __half2float(hi));
}

// ---------------- cp.async helpers ----------------
static __device__ __forceinline__ uint32_t smem_u32(const void* p) {
    uint32_t a;
    asm("{ .reg .u64 t; cvta.to.shared.u64 t, %1; cvt.u32.u64 %0, t; }" : "=r"(a) : "l"(p));
    return a;
}
static __device__ __forceinline__ void cp_async16(uint32_t dst, const void* src) {
    asm volatile("cp.async.cg.shared.global [%0], [%1], 16;\n" :: "r"(dst), "l"(src));
}
#define CP_COMMIT() asm volatile("cp.async.commit_group;\n" ::: "memory")
#define CP_WAIT1()  asm volatile("cp.async.wait_group 1;\n" ::: "memory")

// ---------------- elementwise split kernels ----------------
__device__ __forceinline__ void split_body(const float* __restrict__ src,
                                           __half* __restrict__ hi,
                                           __half* __restrict__ lo, int n) {
    int idx = blockIdx.x * blockDim.x + threadIdx.x;
    if (idx < n) {
        float x = src[idx];
        __half h, l; splitf(x, h, l);
        hi[idx] = h; lo[idx] = l;
    }
}
__global__ void __launch_bounds__(256) split_x_kernel(const float* __restrict__ src) {
    split_body(src, g_Xhi, g_Xlo, MROWS*HID);
}
__global__ void __launch_bounds__(256) split_wqkv_kernel(const float* __restrict__ src) {
    split_body(src, g_Wqkvhi, g_Wqkvlo, QKVN*HID);
}
__global__ void __launch_bounds__(256) split_wo_kernel(const float* __restrict__ src) {
    split_body(src, g_Wohi, g_Wolo, HID*HID);
}

// ---------------- RoPE cos/sin table ----------------
__global__ void __launch_bounds__(256) rope_table_kernel() {
    int idx = blockIdx.x * blockDim.x + threadIdx.x;
    if (idx >= SEQ*64) return;
    int i = idx & 63;
    int s = idx >> 6;
    double inv = pow(10000.0, -((double)(2*i)) / 128.0);
    float invf = (float)inv;
    float ang  = (float)s * invf;
    g_cos[idx] = (float)cos((double)ang);
    g_sin[idx] = (float)sin((double)ang);
}

// =====================================================================
//  Pipelined split-fp16 GEMM: CTA 256x128, 512 threads, warp 64x32.
//  KC=64, 2-stage cp.async. TERMS: 3 or 2 split terms.
//  EPI: 0 = fp32 C direct ; 1 = fused RoPE+transpose+split (Q/K) ;
//       2 = direct fp16 V transpose.
// =====================================================================

#define KC        64
#define GSTAGES   2
#define A_HALF    (256*72)
#define B_HALF    (128*72)
#define STAGE_HALF (2*A_HALF + 2*B_HALF)   /* 55296 */
#define STAGE_BYTES (STAGE_HALF*2)         /* 110592 */
#define GEMM_SMEM (GSTAGES*STAGE_BYTES)    /* 221184 */

static __device__ __forceinline__ void gemm3_load_stage(
    uint32_t stage_base, int tid,
    const __half* __restrict__ Ahi, const __half* __restrict__ Alo,
    const __half* __restrict__ Bhi, const __half* __restrict__ Blo,
    int bm, int bn, int K, int k0)
{
    int chunk = tid & 7;
    int r0    = tid >> 3;
    const char* gAh = (const char*)(Ahi + (size_t)bm * K + k0) + chunk * 16;
    const char* gAl = (const char*)(Alo + (size_t)bm * K + k0) + chunk * 16;
    const char* gBh = (const char*)(Bhi + (size_t)bn * K + k0) + chunk * 16;
    const char* gBl = (const char*)(Blo + (size_t)bn * K + k0) + chunk * 16;
    #pragma unroll
    for (int u = 0; u < 4; u++) {
        int row = r0 + u * 64;
        uint32_t so = (uint32_t)(row * 144 + chunk * 16);
        cp_async16(stage_base + so,              gAh + (size_t)row * K * 2);
        cp_async16(stage_base + 2*A_HALF + so,   gAl + (size_t)row * K * 2);
    }
    #pragma unroll
    for (int u = 0; u < 2; u++) {
        int row = r0 + u * 64;
        uint32_t so = (uint32_t)(row * 144 + chunk * 16);
        cp_async16(stage_base + 4*A_HALF + so,             gBh + (size_t)row * K * 2);
        cp_async16(stage_base + 4*A_HALF + 2*B_HALF + so,  gBl + (size_t)row * K * 2);
    }
}

template<int TERMS, int EPI>
static __device__ __forceinline__ void gemm_body(
    __half* smh, uint32_t smem_base, int tid, int wid,
    const __half* __restrict__ Ahi, const __half* __restrict__ Alo,
    const __half* __restrict__ Bhi, const __half* __restrict__ Blo,
    float* __restrict__ C, int K, int ldc, int bm, int bn)
{
    int wm = (wid >> 2) * 64;
    int wn = (wid & 3) * 32;

    wmma::fragment<wmma::accumulator,16,16,16,float> acc[4][2];
    #pragma unroll
    for (int i = 0; i < 4; i++)
        #pragma unroll
        for (int j = 0; j < 2; j++)
            wmma::fill_fragment(acc[i][j], 0.0f);

    const int NIT = K / KC;

    gemm3_load_stage(smem_base,               tid, Ahi, Alo, Bhi, Blo, bm, bn, K, 0);
    CP_COMMIT();
    gemm3_load_stage(smem_base + STAGE_BYTES, tid, Ahi, Alo, Bhi, Blo, bm, bn, K, KC);
    CP_COMMIT();

    for (int it = 0; it < NIT; it++) {
        CP_WAIT1();
        __syncthreads();

        const __half* st  = smh + (size_t)(it & 1) * STAGE_HALF;
        const __half* sAh = st;
        const __half* sAl = st + A_HALF;
        const __half* sBh = st + 2*A_HALF;
        const __half* sBl = st + 2*A_HALF + B_HALF;

        #pragma unroll
        for (int kk = 0; kk < 4; kk++) {
            wmma::fragment<wmma::matrix_b,16,16,16,__half,wmma::col_major> bh[2], bl[2];
            #pragma unroll
            for (int j = 0; j < 2; j++) {
                wmma::load_matrix_sync(bh[j], sBh + (wn + j*16)*72 + kk*16, 72);
                wmma::load_matrix_sync(bl[j], sBl + (wn + j*16)*72 + kk*16, 72);
            }
            #pragma unroll
            for (int i = 0; i < 4; i++) {
                wmma::fragment<wmma::matrix_a,16,16,16,__half,wmma::row_major> ah, al;
                wmma::load_matrix_sync(ah, sAh + (wm + i*16)*72 + kk*16, 72);
                if (TERMS == 3)
                    wmma::load_matrix_sync(al, sAl + (wm + i*16)*72 + kk*16, 72);
                #pragma unroll
                for (int j = 0; j < 2; j++) {
                    wmma::mma_sync(acc[i][j], ah, bh[j], acc[i][j]);
                    wmma::mma_sync(acc[i][j], ah, bl[j], acc[i][j]);
                    if (TERMS == 3)
                        wmma::mma_sync(acc[i][j], al, bh[j], acc[i][j]);
                }
            }
        }
        __syncthreads();

        int nxt = it + 2;
        if (nxt < NIT)
            gemm3_load_stage(smem_base + (uint32_t)(nxt & 1) * STAGE_BYTES, tid,
                             Ahi, Alo, Bhi, Blo, bm, bn, K, nxt * KC);
        CP_COMMIT();
    }

    if (EPI == 0) {
        #pragma unroll
        for (int i = 0; i < 4; i++)
            #pragma unroll
            for (int j = 0; j < 2; j++) {
                size_t off = (size_t)(bm + wm + i*16) * ldc + bn + wn + j*16;
                wmma::store_matrix_sync(&C[off], acc[i][j], ldc, wmma::mem_row_major);
            }
        return;
    }

    float* sC = (float*)smh;
    #pragma unroll
    for (int i = 0; i < 4; i++)
        #pragma unroll
        for (int j = 0; j < 2; j++)
            wmma::store_matrix_sync(sC + (wm + i*16)*132 + wn + j*16, acc[i][j],
                                    132, wmma::mem_row_major);
    __syncthreads();

    int h = (bn >> 7) & 31;
    if (EPI == 1) {
        bool isk = (bn >= HID);
        __half* Dh = isk ? g_Khi : g_Qhi;
        __half* Dl = isk ? g_Klo : g_Qlo;
        for (int idx = tid; idx < 256*64; idx += 512) {
            int r = idx >> 6, d = idx & 63;
            float x1 = sC[r*132 + d];
            float x2 = sC[r*132 + d + 64];
            int row = bm + r;
            int s   = row & (SEQ-1);
            int b   = row >> 11;
            float c  = g_cos[s*64 + d];
            float sn = g_sin[s*64 + d];
            float o1 = x1*c - x2*sn;
            float o2 = x1*sn + x2*c;
            size_t dst = (((size_t)b * NHEAD + h) * SEQ + s) * HDIM + d;
            __half hi, lo;
            splitf(o1, hi, lo); Dh[dst]    = hi; Dl[dst]    = lo;
            splitf(o2, hi, lo); Dh[dst+64] = hi; Dl[dst+64] = lo;
        }
    } else {
        for (int idx = tid; idx < 256*128; idx += 512) {
            int r = idx >> 7, d = idx & 127;
            int row = bm + r;
            int s   = row & (SEQ-1);
            int b   = row >> 11;
            g_V[(((size_t)b * NHEAD + h) * SEQ + s) * HDIM + d] = __float2half(sC[r*132 + d]);
        }
    }
}

// merged QKV projection: bn < 2*HID -> Q/K (3-term, RoPE epi); else V (2-term)
__global__ void __launch_bounds__(512, 1) gemm_qkv_merged_kernel(
    const __half* __restrict__ Ahi, const __half* __restrict__ Alo,
    const __half* __restrict__ Bhi, const __half* __restrict__ Blo,
    int K, int grid_m, int grid_n)
{
    extern __shared__ __half smh[];
    uint32_t smem_base = smem_u32(smh);
    int tid = threadIdx.x;
    int wid = tid >> 5;

    int pid = blockIdx.x;
    const int GRPW = 8;
    int width = GRPW * grid_n;
    int g   = pid / width;
    int rem = pid - g * width;
    int gm  = grid_m - g * GRPW; if (gm > GRPW) gm = GRPW;
    int bm  = (g * GRPW + (rem % gm)) * 256;
    int bn  = (rem / gm) * 128;

    if (bn < 2*HID)
        gemm_body<3,1>(smh, smem_base, tid, wid, Ahi, Alo, Bhi, Blo,
                       nullptr, K, 0, bm, bn);
    else
        gemm_body<2,2>(smh, smem_base, tid, wid, Ahi, Alo, Bhi, Blo,
                       nullptr, K, 0, bm, bn);
}

// out projection: plain fp32 epilogue
__global__ void __launch_bounds__(512, 1) gemm_out_kernel(
    const __half* __restrict__ Ahi, const __half* __restrict__ Alo,
    const __half* __restrict__ Bhi, const __half* __restrict__ Blo,
    float* __restrict__ C, int K, int ldc, int grid_m, int grid_n)
{
    extern __shared__ __half smh[];
    uint32_t smem_base = smem_u32(smh);
    int tid = threadIdx.x;
    int wid = tid >> 5;

    int pid = blockIdx.x;
    const int GRPW = 8;
    int width = GRPW * grid_n;
    int g   = pid / width;
    int rem = pid - g * width;
    int gm  = grid_m - g * GRPW; if (gm > GRPW) gm = GRPW;
    int bm  = (g * GRPW + (rem % gm)) * 256;
    int bn  = (rem / gm) * 128;

    gemm_body<2,0>(smh, smem_base, tid, wid, Ahi, Alo, Bhi, Blo, C, K, ldc, bm, bn);
}

// ---------------- flash attention, 64-row q tiles, causal, cp.async double buffer ----------------
#define TILE_H   (64*136)
#define TILE_B   (TILE_H*2)
#define FL_SMEM  (8*TILE_B + 64*68*4 + 64*72*2 + 64*132*4 + 3*64*4)

static __device__ __forceinline__ void flash_issue_tile(
    uint32_t dKh, uint32_t dKl, uint32_t dV,
    const __half* __restrict__ Kh, const __half* __restrict__ Kl,
    const __half* __restrict__ V, int tid)
{
    int chunk = tid & 15;
    int r0    = tid >> 4;
    #pragma unroll
    for (int u = 0; u < 4; u++) {
        int r = r0 + u * 16;
        uint32_t so = (uint32_t)(r * 272 + chunk * 16);
        size_t   go = (size_t)r * HDIM * 2 + chunk * 16;
        cp_async16(dKh + so, (const char*)Kh + go);
        cp_async16(dKl + so, (const char*)Kl + go);
        cp_async16(dV  + so, (const char*)V  + go);
    }
}

__global__ void __launch_bounds__(256) flash_kernel() {
    extern __shared__ unsigned char smraw[];
    __half* sQh = (__half*)smraw;
    __half* sQl = sQh + TILE_H;
    __half* sKB = sQl + TILE_H;
    float*  sS  = (float*)(sKB + 6*TILE_H);
    __half* sP  = (__half*)(sS + 64*68);
    float*  sO  = (float*)(sP + 64*72);
    float*  smx = sO + 64*132;
    float*  sl  = smx + 64;

    int tid = threadIdx.x;
    int wid = tid >> 5;
    int qt  = gridDim.x - 1 - blockIdx.x;   // longest CTAs first
    int h   = blockIdx.y;
    int b   = blockIdx.z;
    int bh  = b * NHEAD + h;
    int q0  = qt * 64;

    const float scale = 0.08838834764831845f;

    const __half* Khg = g_Khi + (size_t)bh * SEQ * HDIM;
    const __half* Klg = g_Klo + (size_t)bh * SEQ * HDIM;
    const __half* Vg  = g_V   + (size_t)bh * SEQ * HDIM;

    uint32_t sKB_u = smem_u32(sKB);

    flash_issue_tile(sKB_u, sKB_u + TILE_B, sKB_u + 2*TILE_B, Khg, Klg, Vg, tid);
    CP_COMMIT();

    {
        const __half* Qh = g_Qhi + ((size_t)bh * SEQ + q0) * HDIM;
        const __half* Ql = g_Qlo + ((size_t)bh * SEQ + q0) * HDIM;
        for (int v = tid; v < 1024; v += 256) {
            int r = v >> 4, c = (v & 15) << 3;
            *(int4*)(sQh + r*136 + c) = *(const int4*)(Qh + r*HDIM + c);
            *(int4*)(sQl + r*136 + c) = *(const int4*)(Ql + r*HDIM + c);
        }
    }
    for (int v = tid; v < 64*132; v += 256) sO[v] = 0.0f;
    if (tid < 64) { smx[tid] = -INFINITY; sl[tid] = 0.0f; }

    int wm = (wid >> 1) * 16;

    for (int kt = 0; kt <= qt; kt++) {
        if (kt + 1 <= qt) {
            uint32_t nb = sKB_u + (uint32_t)((kt + 1) & 1) * 3 * TILE_B;
            flash_issue_tile(nb, nb + TILE_B, nb + 2*TILE_B,
                             Khg + (size_t)(kt+1)*64*HDIM,
                             Klg + (size_t)(kt+1)*64*HDIM,
                             Vg  + (size_t)(kt+1)*64*HDIM, tid);
        }
        CP_COMMIT();
        CP_WAIT1();
        __syncthreads();

        __half* sKh = sKB + (size_t)(kt & 1) * 3 * TILE_H;
        __half* sKl = sKh + TILE_H;
        __half* sV  = sKh + 2*TILE_H;

        // S = Q K^T (3-term split)
        {
            int wn = (wid & 1) * 32;
            wmma::fragment<wmma::accumulator,16,16,16,float> sacc[2];
            wmma::fill_fragment(sacc[0], 0.0f);
            wmma::fill_fragment(sacc[1], 0.0f);
            #pragma unroll
            for (int d8 = 0; d8 < 8; d8++) {
                wmma::fragment<wmma::matrix_a,16,16,16,__half,wmma::row_major> ah, al;
                wmma::load_matrix_sync(ah, sQh + wm*136 + d8*16, 136);
                wmma::load_matrix_sync(al, sQl + wm*136 + d8*16, 136);
                #pragma unroll
                for (int j = 0; j < 2; j++) {
                    wmma::fragment<wmma::matrix_b,16,16,16,__half,wmma::col_major> kh, kl;
                    wmma::load_matrix_sync(kh, sKh + (wn + j*16)*136 + d8*16, 136);
                    wmma::load_matrix_sync(kl, sKl + (wn + j*16)*136 + d8*16, 136);
                    wmma::mma_sync(sacc[j], ah, kh, sacc[j]);
                    wmma::mma_sync(sacc[j], ah, kl, sacc[j]);
                    wmma::mma_sync(sacc[j], al, kh, sacc[j]);
                }
            }
            wmma::store_matrix_sync(sS + wm*68 + wn,      sacc[0], 68, wmma::mem_row_major);
            wmma::store_matrix_sync(sS + wm*68 + wn + 16, sacc[1], 68, wmma::mem_row_major);
        }
        __syncthreads();

        // online softmax + fused O rescale (4 threads per row)
        {
            int r    = tid >> 2;
            int lane = tid & 3;
            bool diag = (kt == qt);
            int jmax = diag ? (r + 1) : 64;

            float lm = -INFINITY;
            #pragma unroll
            for (int jj = 0; jj < 16; jj++) {
                int j = lane*16 + jj;
                if (j < jmax) lm = fmaxf(lm, sS[r*68 + j] * scale);
            }
            lm = fmaxf(lm, __shfl_xor_sync(0xffffffffu, lm, 1));
            lm = fmaxf(lm, __shfl_xor_sync(0xffffffffu, lm, 2));
            float mo = smx[r];
            float mn = fmaxf(mo, lm);

            float rl = 0.0f;
            #pragma unroll
            for (int jj = 0; jj < 16; jj++) {
                int j = lane*16 + jj;
                float p = 0.0f;
                if (j < jmax) { p = __expf(sS[r*68 + j] * scale - mn); rl += p; }
                sP[r*72 + j] = __float2half(p);
            }
            rl += __shfl_xor_sync(0xffffffffu, rl, 1);
            rl += __shfl_xor_sync(0xffffffffu, rl, 2);

            float a = __expf(mo - mn);      // all 4 lanes compute alpha
            if (lane == 0) {
                smx[r] = mn;
                sl[r]  = sl[r] * a + rl;
            }
            // fused rescale: each lane scales its 32 O columns of row r
            #pragma unroll
            for (int dd = 0; dd < 32; dd++)
                sO[r*132 + lane*32 + dd] *= a;
        }
        __syncthreads();

        // O += P @ V
        {
            int wn2 = (wid & 1) * 64;
            wmma::fragment<wmma::accumulator,16,16,16,float> oc[4];
            #pragma unroll
            for (int j = 0; j < 4; j++)
                wmma::load_matrix_sync(oc[j], sO + wm*132 + wn2 + j*16, 132, wmma::mem_row_major);
            #pragma unroll
            for (int kk = 0; kk < 4; kk++) {
                wmma::fragment<wmma::matrix_a,16,16,16,__half,wmma::row_major> pf;
                wmma::load_matrix_sync(pf, sP + wm*72 + kk*16, 72);
                #pragma unroll
                for (int j = 0; j < 4; j++) {
                    wmma::fragment<wmma::matrix_b,16,16,16,__half,wmma::row_major> vf;
                    wmma::load_matrix_sync(vf, sV + (kk*16)*136 + wn2 + j*16, 136);
                    wmma::mma_sync(oc[j], pf, vf, oc[j]);
                }
            }
            #pragma unroll
            for (int j = 0; j < 4; j++)
                wmma::store_matrix_sync(sO + wm*132 + wn2 + j*16, oc[j], 132, wmma::mem_row_major);
        }
        __syncthreads();
    }

    for (int v = tid; v < 64*128; v += 256) {
        int r = v >> 7, d = v & 127;
        float o = sO[r*132 + d] / sl[r];
        size_t dst = ((size_t)b * SEQ + q0 + r) * HID + (size_t)h * HDIM + d;
        __half hi, lo; splitf(o, hi, lo);
        g_AOhi[dst] = hi; g_AOlo[dst] = lo;
    }
}

// ---------------- launch ----------------
extern "C" void kernel_launch(void* const* d_in, const int* in_sizes, int n_in,
                              void* d_out, int out_size) {
    const float* X    = (const float*)d_in[0];
    const float* Wqkv = (const float*)d_in[1];
    const float* Wo   = (const float*)d_in[2];

    cudaFuncSetAttribute(flash_kernel, cudaFuncAttributeMaxDynamicSharedMemorySize, FL_SMEM);
    cudaFuncSetAttribute(gemm_qkv_merged_kernel, cudaFuncAttributeMaxDynamicSharedMemorySize, GEMM_SMEM);
    cudaFuncSetAttribute(gemm_out_kernel, cudaFuncAttributeMaxDynamicSharedMemorySize, GEMM_SMEM);

    __half *Xhi, *Xlo, *Wqh, *Wql, *Woh, *Wol, *AOh, *AOl;
    cudaGetSymbolAddress((void**)&Xhi, g_Xhi);
    cudaGetSymbolAddress((void**)&Xlo, g_Xlo);
    cudaGetSymbolAddress((void**)&Wqh, g_Wqkvhi);
    cudaGetSymbolAddress((void**)&Wql, g_Wqkvlo);
    cudaGetSymbolAddress((void**)&Woh, g_Wohi);
    cudaGetSymbolAddress((void**)&Wol, g_Wolo);
    cudaGetSymbolAddress((void**)&AOh, g_AOhi);
    cudaGetSymbolAddress((void**)&AOl, g_AOlo);

    split_x_kernel   <<<(MROWS*HID + 255)/256, 256>>>(X);
    split_wqkv_kernel<<<(QKVN*HID  + 255)/256, 256>>>(Wqkv);
    split_wo_kernel  <<<(HID*HID   + 255)/256, 256>>>(Wo);
    rope_table_kernel<<<(SEQ*64    + 255)/256, 256>>>();

    // full QKV projection in one launch (M=4096, N=12288)
    gemm_qkv_merged_kernel<<<(MROWS/256)*(QKVN/128), 512, GEMM_SMEM>>>(
        Xhi, Xlo, Wqh, Wql, HID, MROWS/256, QKVN/128);

    flash_kernel<<<dim3(SEQ/64, NHEAD, BATCH), 256, FL_SMEM>>>();

    // Output projection (N=4096): 2-term, direct fp32 store
    gemm_out_kernel<<<(MROWS/256)*(HID/128), 512, GEMM_SMEM>>>(
        AOh, AOl, Woh, Wol, (float*)d_out, HID, HID, MROWS/256, HID/128);
}